// round 3
// baseline (speedup 1.0000x reference)
#include <cuda_runtime.h>
#include <cuda_bf16.h>

// Problem constants
#define T_   4
#define B_   32
#define C_   384
#define N_   256
#define TB_  128         // T_*B_
#define HEADS 8
#define CH   48          // C_/HEADS
#define BCN  3145728     // B_*C_*N_
#define TBCN 12582912    // T_*B_*C_*N_

typedef unsigned long long ull;

// Scratch (device globals, no allocations allowed)
__device__ float g_qlin[TBCN];
__device__ float g_klin[TBCN];
__device__ float g_ybuf[TBCN];

// ---------------------------------------------------------------------------
// Packed fp32x2 helpers (sm_103a FFMA2 path, per-lane IEEE fp32 FMA)
// ---------------------------------------------------------------------------
__device__ __forceinline__ ull pack2(float x) {
    ull r;
    asm("mov.b64 %0, {%1, %1};" : "=l"(r) : "f"(x));
    return r;
}
__device__ __forceinline__ void fma2(ull& d, ull a, ull b) {
    asm("fma.rn.f32x2 %0, %1, %2, %0;" : "+l"(d) : "l"(a), "l"(b));
}
__device__ __forceinline__ float2 unpack2(ull v) {
    float2 f;
    asm("mov.b64 {%0, %1}, %2;" : "=f"(f.x), "=f"(f.y) : "l"(v));
    return f;
}

// ---------------------------------------------------------------------------
// SGEMM with fused BatchNorm (+ optional bias) epilogue, FFMA2 inner loop.
// out[tb, d, n] = BN( sum_c W[d,c] * X[tb, c, n]  (+ bias[d]) )
// Tile: BM=128 (d) x BN=128 (n) x BK=8 (c); 256 threads; 8x8 per thread.
// A is stored in smem PRE-DUPLICATED as f32x2 pairs so the inner loop is
// pure LDS + FFMA2 (no per-FMA packing MOVs).
// ---------------------------------------------------------------------------
#define BM 128
#define BNN 128
#define BK 8

__global__ __launch_bounds__(256, 2)
void gemm_bn_kernel(const float* __restrict__ X,
                    const float* __restrict__ W,
                    const float* __restrict__ gamma,
                    const float* __restrict__ beta,
                    const float* __restrict__ mean,
                    const float* __restrict__ var,
                    const float* __restrict__ bias,   // may be nullptr
                    float* __restrict__ out)
{
    const int tb = blockIdx.z;
    const int d0 = blockIdx.y * BM;
    const int n0 = blockIdx.x * BNN;

    const float* Xb = X   + (size_t)tb * C_ * N_;
    float*       Ob = out + (size_t)tb * C_ * N_;

    // A duplicated: As2[buf][k][m] = {W, W} as packed f32x2 (8B each)
    __shared__ __align__(16) ull   As2[2][BK][BM];
    __shared__ __align__(16) float Bs [2][BK][BNN];

    const int tid = threadIdx.x;

    // A-load: 128 rows x 8 cols = 256 float4 (2 per row)
    const int aRow  = tid >> 1;
    const int aCol4 = (tid & 1) * 4;
    // B-load: 8 rows x 128 cols = 256 float4
    const int bRow  = tid >> 5;
    const int bCol  = (tid & 31) * 4;

    const int tm0 = (tid >> 4) * 8;
    const int tn0 = (tid & 15) * 8;

    // Packed accumulators: acc[i][j] holds columns {tn0+2j, tn0+2j+1} of row tm0+i
    ull acc[8][4];
#pragma unroll
    for (int i = 0; i < 8; i++)
#pragma unroll
        for (int j = 0; j < 4; j++) acc[i][j] = 0ull;

    // Preload k-block 0 into buffer 0 (A duplicated at store time)
    {
        float4 a4 = *(const float4*)(W  + (size_t)(d0 + aRow) * C_ + aCol4);
        float4 b4 = *(const float4*)(Xb + (size_t)bRow * N_ + n0 + bCol);
        As2[0][aCol4 + 0][aRow] = pack2(a4.x);
        As2[0][aCol4 + 1][aRow] = pack2(a4.y);
        As2[0][aCol4 + 2][aRow] = pack2(a4.z);
        As2[0][aCol4 + 3][aRow] = pack2(a4.w);
        *(float4*)&Bs[0][bRow][bCol] = b4;
    }
    __syncthreads();

    int buf = 0;
    const int NKB = C_ / BK;   // 48
    for (int kb = 0; kb < NKB; ++kb) {
        const int c0n = (kb + 1) * BK;
        float4 a4n, b4n;
        const bool more = (c0n < C_);
        if (more) {
            a4n = *(const float4*)(W  + (size_t)(d0 + aRow) * C_ + c0n + aCol4);
            b4n = *(const float4*)(Xb + (size_t)(c0n + bRow) * N_ + n0 + bCol);
        }

#pragma unroll
        for (int k = 0; k < BK; k++) {
            // A fragment: 8 pre-duplicated f32x2 values (4 x LDS.128, broadcast)
            ulonglong2 aa0 = *(const ulonglong2*)&As2[buf][k][tm0];
            ulonglong2 aa1 = *(const ulonglong2*)&As2[buf][k][tm0 + 2];
            ulonglong2 aa2 = *(const ulonglong2*)&As2[buf][k][tm0 + 4];
            ulonglong2 aa3 = *(const ulonglong2*)&As2[buf][k][tm0 + 6];
            // B fragment: 8 floats = 4 packed pairs (2 x LDS.128)
            ulonglong2 bb0 = *(const ulonglong2*)&Bs[buf][k][tn0];
            ulonglong2 bb1 = *(const ulonglong2*)&Bs[buf][k][tn0 + 4];
            const ull bp0 = bb0.x, bp1 = bb0.y, bp2 = bb1.x, bp3 = bb1.y;
            ull av[8];
            av[0]=aa0.x; av[1]=aa0.y; av[2]=aa1.x; av[3]=aa1.y;
            av[4]=aa2.x; av[5]=aa2.y; av[6]=aa3.x; av[7]=aa3.y;
#pragma unroll
            for (int i = 0; i < 8; i++) {
                fma2(acc[i][0], av[i], bp0);
                fma2(acc[i][1], av[i], bp1);
                fma2(acc[i][2], av[i], bp2);
                fma2(acc[i][3], av[i], bp3);
            }
        }

        if (more) {
            const int nb = buf ^ 1;
            As2[nb][aCol4 + 0][aRow] = pack2(a4n.x);
            As2[nb][aCol4 + 1][aRow] = pack2(a4n.y);
            As2[nb][aCol4 + 2][aRow] = pack2(a4n.z);
            As2[nb][aCol4 + 3][aRow] = pack2(a4n.w);
            *(float4*)&Bs[nb][bRow][bCol] = b4n;
            __syncthreads();
            buf = nb;
        }
    }

    // Epilogue: BN (+ bias folded)
#pragma unroll
    for (int i = 0; i < 8; i++) {
        const int d = d0 + tm0 + i;
        const float sc = gamma[d] * rsqrtf(var[d] + 1e-5f);
        float sh = beta[d] - mean[d] * sc;
        if (bias) sh = fmaf(sc, bias[d], sh);
        float2 p0 = unpack2(acc[i][0]);
        float2 p1 = unpack2(acc[i][1]);
        float2 p2 = unpack2(acc[i][2]);
        float2 p3 = unpack2(acc[i][3]);
        float4 o0, o1;
        o0.x = fmaf(p0.x, sc, sh);
        o0.y = fmaf(p0.y, sc, sh);
        o0.z = fmaf(p1.x, sc, sh);
        o0.w = fmaf(p1.y, sc, sh);
        o1.x = fmaf(p2.x, sc, sh);
        o1.y = fmaf(p2.y, sc, sh);
        o1.z = fmaf(p3.x, sc, sh);
        o1.w = fmaf(p3.y, sc, sh);
        float* op = Ob + (size_t)d * N_ + n0 + tn0;
        *(float4*)(op)     = o0;
        *(float4*)(op + 4) = o1;
    }
}

// ---------------------------------------------------------------------------
// Fused: q-LIF (vth=1) -> head-sum over Ch -> attn-LIF (vth=0.5) -> k-LIF ->
// y = attn * k_spike.  One thread per (b, head, n); block = one (b, head).
// ---------------------------------------------------------------------------
__global__ void attn_fuse_kernel(const float* __restrict__ qlin,
                                 const float* __restrict__ klin,
                                 float* __restrict__ y)
{
    const int bh = blockIdx.x;
    const int b  = bh >> 3;
    const int hd = bh & 7;
    const int n  = threadIdx.x;
    const size_t tstr = (size_t)BCN;

    float qs[4] = {0.f, 0.f, 0.f, 0.f};
    const size_t base = ((size_t)b * C_ + hd * CH) * N_ + n;

    for (int c = 0; c < CH; ++c) {
        const size_t idx = base + (size_t)c * N_;
        float v = 0.f;
#pragma unroll
        for (int t = 0; t < T_; ++t) {
            const float xq = qlin[idx + (size_t)t * tstr];
            const float h  = v + (xq - v) * 0.5f;
            const bool  sp = (h >= 1.0f);
            qs[t] += sp ? 1.f : 0.f;
            v = sp ? 0.f : h;
        }
    }

    float a[4];
    {
        float v = 0.f;
#pragma unroll
        for (int t = 0; t < T_; ++t) {
            const float h = v + (qs[t] - v) * 0.5f;
            const bool sp = (h >= 0.5f);
            a[t] = sp ? 1.f : 0.f;
            v = sp ? 0.f : h;
        }
    }

    for (int c = 0; c < CH; ++c) {
        const size_t idx = base + (size_t)c * N_;
        float v = 0.f;
#pragma unroll
        for (int t = 0; t < T_; ++t) {
            const float xk = klin[idx + (size_t)t * tstr];
            const float h  = v + (xk - v) * 0.5f;
            const bool  sp = (h >= 1.0f);
            y[idx + (size_t)t * tstr] = (sp ? 1.f : 0.f) * a[t];
            v = sp ? 0.f : h;
        }
    }
}

// ---------------------------------------------------------------------------
// Final LIF over T on proj output -> spikes to d_out
// ---------------------------------------------------------------------------
__global__ void final_lif_kernel(const float* __restrict__ p,
                                 float* __restrict__ o)
{
    const size_t i = (size_t)blockIdx.x * blockDim.x + threadIdx.x;
    float v = 0.f;
#pragma unroll
    for (int t = 0; t < T_; ++t) {
        const float x = p[i + (size_t)t * BCN];
        const float h = v + (x - v) * 0.5f;
        const bool sp = (h >= 1.0f);
        o[i + (size_t)t * BCN] = sp ? 1.f : 0.f;
        v = sp ? 0.f : h;
    }
}

// ---------------------------------------------------------------------------
extern "C" void kernel_launch(void* const* d_in, const int* in_sizes, int n_in,
                              void* d_out, int out_size)
{
    const float* x        = (const float*)d_in[0];
    const float* q_w      = (const float*)d_in[1];
    const float* q_gamma  = (const float*)d_in[2];
    const float* q_beta   = (const float*)d_in[3];
    const float* q_mean   = (const float*)d_in[4];
    const float* q_var    = (const float*)d_in[5];
    const float* k_w      = (const float*)d_in[6];
    const float* k_gamma  = (const float*)d_in[7];
    const float* k_beta   = (const float*)d_in[8];
    const float* k_mean   = (const float*)d_in[9];
    const float* k_var    = (const float*)d_in[10];
    const float* p_w      = (const float*)d_in[11];
    const float* p_gamma  = (const float*)d_in[12];
    const float* p_beta   = (const float*)d_in[13];
    const float* p_mean   = (const float*)d_in[14];
    const float* p_var    = (const float*)d_in[15];
    const float* p_b      = (const float*)d_in[16];

    float *qlin, *klin, *ybuf;
    cudaGetSymbolAddress((void**)&qlin, g_qlin);
    cudaGetSymbolAddress((void**)&klin, g_klin);
    cudaGetSymbolAddress((void**)&ybuf, g_ybuf);

    dim3 grid(N_ / BNN, C_ / BM, TB_);   // (2, 3, 128)

    gemm_bn_kernel<<<grid, 256>>>(x, q_w, q_gamma, q_beta, q_mean, q_var,
                                  nullptr, qlin);
    gemm_bn_kernel<<<grid, 256>>>(x, k_w, k_gamma, k_beta, k_mean, k_var,
                                  nullptr, klin);

    attn_fuse_kernel<<<B_ * HEADS, N_>>>(qlin, klin, ybuf);

    gemm_bn_kernel<<<grid, 256>>>(ybuf, p_w, p_gamma, p_beta, p_mean, p_var,
                                  p_b, qlin);

    final_lif_kernel<<<BCN / 256, 256>>>(qlin, (float*)d_out);
}

// round 4
// speedup vs baseline: 1.1697x; 1.1697x over previous
#include <cuda_runtime.h>
#include <cuda_bf16.h>

// Problem constants
#define T_   4
#define B_   32
#define C_   384
#define N_   256
#define TB_  128         // T_*B_
#define HEADS 8
#define CH   48          // C_/HEADS
#define BCN  3145728     // B_*C_*N_
#define TBCN 12582912    // T_*B_*C_*N_

typedef unsigned long long ull;

// Scratch (device globals, no allocations allowed)
__device__ float g_qlin[TBCN];
__device__ float g_klin[TBCN];
__device__ float g_ybuf[TBCN];

// ---------------------------------------------------------------------------
// Packed fp32x2 helpers (sm_103a FFMA2 path, per-lane IEEE fp32 FMA)
// ---------------------------------------------------------------------------
__device__ __forceinline__ ull pack2(float x) {
    ull r;
    asm("mov.b64 %0, {%1, %1};" : "=l"(r) : "f"(x));
    return r;
}
__device__ __forceinline__ void fma2(ull& d, ull a, ull b) {
    asm("fma.rn.f32x2 %0, %1, %2, %0;" : "+l"(d) : "l"(a), "l"(b));
}
__device__ __forceinline__ float2 unpack2(ull v) {
    float2 f;
    asm("mov.b64 {%0, %1}, %2;" : "=f"(f.x), "=f"(f.y) : "l"(v));
    return f;
}

// ---------------------------------------------------------------------------
// SGEMM with fused BatchNorm (+ optional bias) epilogue, FFMA2 inner loop.
// out[tb, d, n] = BN( sum_c W[d,c] * X[tb, c, n]  (+ bias[d]) )
// Tile: BM=128 (d) x BN=128 (n) x BK=8 (c); 256 threads; 8x8 per thread.
// Lane mapping chosen for smem-crossbar broadcast dedup:
//   warp = 4(m) x 8(n) lanes ; warps tiled 4(m) x 2(n)
//   -> A addresses shared by 8 lanes, B addresses shared by 4 lanes.
// ---------------------------------------------------------------------------
#define BM 128
#define BNN 128
#define BK 8

__global__ __launch_bounds__(256, 2)
void gemm_bn_kernel(const float* __restrict__ X,
                    const float* __restrict__ W,
                    const float* __restrict__ gamma,
                    const float* __restrict__ beta,
                    const float* __restrict__ mean,
                    const float* __restrict__ var,
                    const float* __restrict__ bias,   // may be nullptr
                    float* __restrict__ out)
{
    const int tb = blockIdx.z;
    const int d0 = blockIdx.y * BM;
    const int n0 = blockIdx.x * BNN;

    const float* Xb = X   + (size_t)tb * C_ * N_;
    float*       Ob = out + (size_t)tb * C_ * N_;

    __shared__ __align__(16) float As[2][BK][BM];
    __shared__ __align__(16) float Bs[2][BK][BNN];

    const int tid  = threadIdx.x;
    const int warp = tid >> 5;
    const int lane = tid & 31;

    // Global-load mappings (unchanged)
    const int aRow  = tid >> 1;          // 0..127
    const int aCol4 = (tid & 1) * 4;     // 0 or 4
    const int bRow  = tid >> 5;          // 0..7
    const int bCol  = (tid & 31) * 4;    // 0..124

    // Compute-lane mapping: broadcast-friendly
    const int wm = warp & 3;             // 0..3
    const int wn = warp >> 2;            // 0..1
    const int m_idx = wm * 4 + (lane >> 3);   // 0..15
    const int n_idx = wn * 8 + (lane & 7);    // 0..15
    const int tm0 = m_idx * 8;
    const int tn0 = n_idx * 8;

    // Packed accumulators: acc[i][j] holds columns {tn0+2j, tn0+2j+1} of row tm0+i
    ull acc[8][4];
#pragma unroll
    for (int i = 0; i < 8; i++)
#pragma unroll
        for (int j = 0; j < 4; j++) acc[i][j] = 0ull;

    // Preload k-block 0 into buffer 0
    {
        float4 a4 = *(const float4*)(W  + (size_t)(d0 + aRow) * C_ + aCol4);
        float4 b4 = *(const float4*)(Xb + (size_t)bRow * N_ + n0 + bCol);
        As[0][aCol4 + 0][aRow] = a4.x;
        As[0][aCol4 + 1][aRow] = a4.y;
        As[0][aCol4 + 2][aRow] = a4.z;
        As[0][aCol4 + 3][aRow] = a4.w;
        *(float4*)&Bs[0][bRow][bCol] = b4;
    }
    __syncthreads();

    int buf = 0;
    const int NKB = C_ / BK;   // 48
    for (int kb = 0; kb < NKB; ++kb) {
        const int c0n = (kb + 1) * BK;
        float4 a4n, b4n;
        const bool more = (c0n < C_);
        if (more) {
            a4n = *(const float4*)(W  + (size_t)(d0 + aRow) * C_ + c0n + aCol4);
            b4n = *(const float4*)(Xb + (size_t)(c0n + bRow) * N_ + n0 + bCol);
        }

#pragma unroll
        for (int k = 0; k < BK; k++) {
            float4 av0 = *(const float4*)&As[buf][k][tm0];
            float4 av1 = *(const float4*)&As[buf][k][tm0 + 4];
            ulonglong2 bb0 = *(const ulonglong2*)&Bs[buf][k][tn0];
            ulonglong2 bb1 = *(const ulonglong2*)&Bs[buf][k][tn0 + 4];
            const ull bp0 = bb0.x, bp1 = bb0.y, bp2 = bb1.x, bp3 = bb1.y;
            float av[8];
            av[0]=av0.x; av[1]=av0.y; av[2]=av0.z; av[3]=av0.w;
            av[4]=av1.x; av[5]=av1.y; av[6]=av1.z; av[7]=av1.w;
#pragma unroll
            for (int i = 0; i < 8; i++) {
                const ull a2 = pack2(av[i]);
                fma2(acc[i][0], a2, bp0);
                fma2(acc[i][1], a2, bp1);
                fma2(acc[i][2], a2, bp2);
                fma2(acc[i][3], a2, bp3);
            }
        }

        if (more) {
            const int nb = buf ^ 1;
            As[nb][aCol4 + 0][aRow] = a4n.x;
            As[nb][aCol4 + 1][aRow] = a4n.y;
            As[nb][aCol4 + 2][aRow] = a4n.z;
            As[nb][aCol4 + 3][aRow] = a4n.w;
            *(float4*)&Bs[nb][bRow][bCol] = b4n;
            __syncthreads();
            buf = nb;
        }
    }

    // Epilogue: BN (+ bias folded)
#pragma unroll
    for (int i = 0; i < 8; i++) {
        const int d = d0 + tm0 + i;
        const float sc = gamma[d] * rsqrtf(var[d] + 1e-5f);
        float sh = beta[d] - mean[d] * sc;
        if (bias) sh = fmaf(sc, bias[d], sh);
        float2 p0 = unpack2(acc[i][0]);
        float2 p1 = unpack2(acc[i][1]);
        float2 p2 = unpack2(acc[i][2]);
        float2 p3 = unpack2(acc[i][3]);
        float4 o0, o1;
        o0.x = fmaf(p0.x, sc, sh);
        o0.y = fmaf(p0.y, sc, sh);
        o0.z = fmaf(p1.x, sc, sh);
        o0.w = fmaf(p1.y, sc, sh);
        o1.x = fmaf(p2.x, sc, sh);
        o1.y = fmaf(p2.y, sc, sh);
        o1.z = fmaf(p3.x, sc, sh);
        o1.w = fmaf(p3.y, sc, sh);
        float* op = Ob + (size_t)d * N_ + n0 + tn0;
        *(float4*)(op)     = o0;
        *(float4*)(op + 4) = o1;
    }
}

// ---------------------------------------------------------------------------
// Fused: q-LIF (vth=1) -> head-sum over Ch -> attn-LIF (vth=0.5) -> k-LIF ->
// y = attn * k_spike.  One thread per (b, head, n); block = one (b, head).
// ---------------------------------------------------------------------------
__global__ void attn_fuse_kernel(const float* __restrict__ qlin,
                                 const float* __restrict__ klin,
                                 float* __restrict__ y)
{
    const int bh = blockIdx.x;
    const int b  = bh >> 3;
    const int hd = bh & 7;
    const int n  = threadIdx.x;
    const size_t tstr = (size_t)BCN;

    float qs[4] = {0.f, 0.f, 0.f, 0.f};
    const size_t base = ((size_t)b * C_ + hd * CH) * N_ + n;

    for (int c = 0; c < CH; ++c) {
        const size_t idx = base + (size_t)c * N_;
        float v = 0.f;
#pragma unroll
        for (int t = 0; t < T_; ++t) {
            const float xq = qlin[idx + (size_t)t * tstr];
            const float h  = v + (xq - v) * 0.5f;
            const bool  sp = (h >= 1.0f);
            qs[t] += sp ? 1.f : 0.f;
            v = sp ? 0.f : h;
        }
    }

    float a[4];
    {
        float v = 0.f;
#pragma unroll
        for (int t = 0; t < T_; ++t) {
            const float h = v + (qs[t] - v) * 0.5f;
            const bool sp = (h >= 0.5f);
            a[t] = sp ? 1.f : 0.f;
            v = sp ? 0.f : h;
        }
    }

    for (int c = 0; c < CH; ++c) {
        const size_t idx = base + (size_t)c * N_;
        float v = 0.f;
#pragma unroll
        for (int t = 0; t < T_; ++t) {
            const float xk = klin[idx + (size_t)t * tstr];
            const float h  = v + (xk - v) * 0.5f;
            const bool  sp = (h >= 1.0f);
            y[idx + (size_t)t * tstr] = (sp ? 1.f : 0.f) * a[t];
            v = sp ? 0.f : h;
        }
    }
}

// ---------------------------------------------------------------------------
// Final LIF over T on proj output -> spikes to d_out
// ---------------------------------------------------------------------------
__global__ void final_lif_kernel(const float* __restrict__ p,
                                 float* __restrict__ o)
{
    const size_t i = (size_t)blockIdx.x * blockDim.x + threadIdx.x;
    float v = 0.f;
#pragma unroll
    for (int t = 0; t < T_; ++t) {
        const float x = p[i + (size_t)t * BCN];
        const float h = v + (x - v) * 0.5f;
        const bool sp = (h >= 1.0f);
        o[i + (size_t)t * BCN] = sp ? 1.f : 0.f;
        v = sp ? 0.f : h;
    }
}

// ---------------------------------------------------------------------------
extern "C" void kernel_launch(void* const* d_in, const int* in_sizes, int n_in,
                              void* d_out, int out_size)
{
    const float* x        = (const float*)d_in[0];
    const float* q_w      = (const float*)d_in[1];
    const float* q_gamma  = (const float*)d_in[2];
    const float* q_beta   = (const float*)d_in[3];
    const float* q_mean   = (const float*)d_in[4];
    const float* q_var    = (const float*)d_in[5];
    const float* k_w      = (const float*)d_in[6];
    const float* k_gamma  = (const float*)d_in[7];
    const float* k_beta   = (const float*)d_in[8];
    const float* k_mean   = (const float*)d_in[9];
    const float* k_var    = (const float*)d_in[10];
    const float* p_w      = (const float*)d_in[11];
    const float* p_gamma  = (const float*)d_in[12];
    const float* p_beta   = (const float*)d_in[13];
    const float* p_mean   = (const float*)d_in[14];
    const float* p_var    = (const float*)d_in[15];
    const float* p_b      = (const float*)d_in[16];

    float *qlin, *klin, *ybuf;
    cudaGetSymbolAddress((void**)&qlin, g_qlin);
    cudaGetSymbolAddress((void**)&klin, g_klin);
    cudaGetSymbolAddress((void**)&ybuf, g_ybuf);

    dim3 grid(N_ / BNN, C_ / BM, TB_);   // (2, 3, 128)

    gemm_bn_kernel<<<grid, 256>>>(x, q_w, q_gamma, q_beta, q_mean, q_var,
                                  nullptr, qlin);
    gemm_bn_kernel<<<grid, 256>>>(x, k_w, k_gamma, k_beta, k_mean, k_var,
                                  nullptr, klin);

    attn_fuse_kernel<<<B_ * HEADS, N_>>>(qlin, klin, ybuf);

    gemm_bn_kernel<<<grid, 256>>>(ybuf, p_w, p_gamma, p_beta, p_mean, p_var,
                                  p_b, qlin);

    final_lif_kernel<<<BCN / 256, 256>>>(qlin, (float*)d_out);
}

// round 6
// speedup vs baseline: 1.4999x; 1.2822x over previous
#include <cuda_runtime.h>
#include <cuda_bf16.h>
#include <cstdint>

// Problem constants
#define T_    4
#define B_    32
#define C_    384
#define N_    256
#define TB_   128
#define HEADS 8
#define CH    48
#define BCN   3145728
#define TBCN  12582912

// ------------------------- device global scratch ---------------------------
__device__ float g_qlin[TBCN];
__device__ float g_klin[TBCN];
__device__ __nv_bfloat16 g_xs[3u * TBCN];       // x splits, [3][tb][n][c]
__device__ __nv_bfloat16 g_yT[TBCN];            // y transposed, [tb][n][c]
__device__ __nv_bfloat16 g_Aq[C_ * 3 * C_];     // [d][3*384] W-split concat
__device__ __nv_bfloat16 g_Ak[C_ * 3 * C_];
__device__ __nv_bfloat16 g_Ap[C_ * 3 * C_];

// ------------------------- PTX helpers (generic sm_80+) --------------------
__device__ __forceinline__ uint32_t smem_to_u32(const void* p) {
    uint32_t a;
    asm("{ .reg .u64 t; cvta.to.shared.u64 t, %1; cvt.u32.u64 %0, t; }"
        : "=r"(a) : "l"(p));
    return a;
}
__device__ __forceinline__ void cp_async16(uint32_t dst, const void* src) {
    asm volatile("cp.async.cg.shared.global [%0], [%1], 16;"
                 :: "r"(dst), "l"(src));
}
__device__ __forceinline__ void ldsm_x4(uint32_t& r0, uint32_t& r1,
                                        uint32_t& r2, uint32_t& r3,
                                        uint32_t addr) {
    asm volatile("ldmatrix.sync.aligned.m8n8.x4.shared.b16 {%0,%1,%2,%3}, [%4];"
                 : "=r"(r0), "=r"(r1), "=r"(r2), "=r"(r3) : "r"(addr));
}
__device__ __forceinline__ void mma16816(float* d,
                                         uint32_t a0, uint32_t a1,
                                         uint32_t a2, uint32_t a3,
                                         uint32_t b0, uint32_t b1) {
    asm volatile(
        "mma.sync.aligned.m16n8k16.row.col.f32.bf16.bf16.f32 "
        "{%0,%1,%2,%3}, {%4,%5,%6,%7}, {%8,%9}, {%0,%1,%2,%3};"
        : "+f"(d[0]), "+f"(d[1]), "+f"(d[2]), "+f"(d[3])
        : "r"(a0), "r"(a1), "r"(a2), "r"(a3), "r"(b0), "r"(b1));
}

// ---------------------------------------------------------------------------
// prep: split fp32 weight [384,384] into 3 exact bf16 terms, K-concat layout
// ---------------------------------------------------------------------------
__global__ void split_w_kernel(const float* __restrict__ W,
                               __nv_bfloat16* __restrict__ A)
{
    int i = blockIdx.x * 256 + threadIdx.x;
    if (i >= C_ * C_) return;
    int d = i / C_, c = i % C_;
    float w = W[i];
    __nv_bfloat16 b1 = __float2bfloat16(w);
    float r = w - __bfloat162float(b1);
    __nv_bfloat16 b2 = __float2bfloat16(r);
    float r2 = r - __bfloat162float(b2);
    __nv_bfloat16 b3 = __float2bfloat16(r2);
    size_t base = (size_t)d * (3 * C_) + c;
    A[base]          = b1;
    A[base + C_]     = b2;
    A[base + 2 * C_] = b3;
}

// ---------------------------------------------------------------------------
// prep: transpose + 3-way bf16 split of x:  x[tb, c, n] -> xs[j][tb, n, c]
// ---------------------------------------------------------------------------
__global__ void split_x_kernel(const float* __restrict__ x,
                               __nv_bfloat16* __restrict__ xs)
{
    __shared__ float tile[64][65];
    const int n0 = blockIdx.x * 64;
    const int c0 = blockIdx.y * 64;
    const int tb = blockIdx.z;
    const float* xb = x + (size_t)tb * C_ * N_;
    const int t = threadIdx.x;

#pragma unroll
    for (int i = 0; i < 16; ++i) {
        int cl = i * 4 + (t >> 6);
        int nl = t & 63;
        tile[cl][nl] = xb[(size_t)(c0 + cl) * N_ + n0 + nl];
    }
    __syncthreads();

#pragma unroll
    for (int i = 0; i < 16; ++i) {
        int nl = i * 4 + (t >> 6);
        int cl = t & 63;
        float v = tile[cl][nl];
        __nv_bfloat16 b1 = __float2bfloat16(v);
        float r = v - __bfloat162float(b1);
        __nv_bfloat16 b2 = __float2bfloat16(r);
        float r2 = r - __bfloat162float(b2);
        __nv_bfloat16 b3 = __float2bfloat16(r2);
        size_t o = ((size_t)tb * N_ + n0 + nl) * C_ + c0 + cl;
        xs[o]                    = b1;
        xs[o + (size_t)TBCN]     = b2;
        xs[o + 2 * (size_t)TBCN] = b3;
    }
}

// ---------------------------------------------------------------------------
// Tensor-core (HMMA mma.sync) GEMM + BN epilogue, exact bf16 split.
// out[tb, d, n] = BN( sum_{terms} W_i[d,:] . X_j[tb, n, :] (+bias) )
// CTA tile 128(d) x 128(n); BK=64; 8 warps (4m x 2n), warp tile 32x64.
// A: [384][3*384] bf16 (W splits K-concat); B: xs [3][tb][n][384] or yT.
// Chunks: kc -> term t = kc/6, ksub = kc%6 (64-col slab of K=384).
// ---------------------------------------------------------------------------
#define ABUF_BYTES 16384    // 128 rows x 128B
#define BUF_BYTES  32768    // A + B
#define GSMEM      65536    // double buffered

__device__ __forceinline__ void load_chunk(const __nv_bfloat16* Ag,
                                           const __nv_bfloat16* Bg,
                                           uint32_t sbase, int buf, int tid)
{
    uint32_t abuf = sbase + (uint32_t)buf * BUF_BYTES;
    uint32_t bbuf = abuf + ABUF_BYTES;
#pragma unroll
    for (int q = 0; q < 4; ++q) {
        int idx = q * 256 + tid;
        int row = idx >> 3, seg = idx & 7;
        uint32_t off = (uint32_t)(row * 128) + (uint32_t)((seg ^ (row & 7)) << 4);
        cp_async16(abuf + off, (const char*)Ag + (size_t)row * 2304 + seg * 16);
        cp_async16(bbuf + off, (const char*)Bg + (size_t)row * 768  + seg * 16);
    }
}

__global__ __launch_bounds__(256, 2)
void gemm_mma_kernel(const __nv_bfloat16* __restrict__ A,
                     const __nv_bfloat16* __restrict__ Bx,
                     int sixterm,
                     const float* __restrict__ gamma,
                     const float* __restrict__ beta,
                     const float* __restrict__ mean,
                     const float* __restrict__ var,
                     const float* __restrict__ bias,
                     float* __restrict__ out)
{
    extern __shared__ char smem[];
    const uint32_t sbase = smem_to_u32(smem);
    const int tid  = threadIdx.x;
    const int wid  = tid >> 5;
    const int lane = tid & 31;
    const int nT = blockIdx.x, mT = blockIdx.y, tb = blockIdx.z;
    const int d0  = mT * 128;
    const int n0g = nT * 128;
    const int wm = wid & 3;          // 0..3 (m)
    const int wn = wid >> 2;         // 0..1 (n)

    const int IMAP[6] = {0, 0, 1, 0, 1, 2};
    const int JMAP[6] = {0, 1, 0, 2, 1, 0};
    const int nch = sixterm ? 36 : 18;

    float acc[2][8][4];
#pragma unroll
    for (int i = 0; i < 2; ++i)
#pragma unroll
        for (int p = 0; p < 8; ++p)
#pragma unroll
            for (int q = 0; q < 4; ++q) acc[i][p][q] = 0.f;

    // prologue: chunk 0 -> buf 0
    {
        const __nv_bfloat16* Ag = A + (size_t)d0 * 1152;           // i=0, ksub=0
        const __nv_bfloat16* Bg = Bx + ((size_t)tb * N_ + n0g) * C_;
        load_chunk(Ag, Bg, sbase, 0, tid);
        asm volatile("cp.async.commit_group;");
    }

    int buf = 0;
    for (int kc = 0; kc < nch; ++kc) {
        if (kc + 1 < nch) {
            const int kn = kc + 1;
            const int t = kn / 6, ksub = kn % 6;
            const int i = sixterm ? IMAP[t] : t;
            const int j = sixterm ? JMAP[t] : 0;
            const __nv_bfloat16* Ag = A + (size_t)d0 * 1152 + i * 384 + ksub * 64;
            const __nv_bfloat16* Bg = Bx + (size_t)j * TBCN +
                                      ((size_t)tb * N_ + n0g) * C_ + ksub * 64;
            load_chunk(Ag, Bg, sbase, buf ^ 1, tid);
            asm volatile("cp.async.commit_group;");
            asm volatile("cp.async.wait_group 1;");
        } else {
            asm volatile("cp.async.wait_group 0;");
        }
        __syncthreads();

        const uint32_t abuf = sbase + (uint32_t)buf * BUF_BYTES;
        const uint32_t bbuf = abuf + ABUF_BYTES;

#pragma unroll
        for (int kk = 0; kk < 4; ++kk) {
            uint32_t a[2][4];
#pragma unroll
            for (int i = 0; i < 2; ++i) {
                int row = wm * 32 + i * 16 + (lane & 15);
                int seg = kk * 2 + (lane >> 4);
                uint32_t addr = abuf + (uint32_t)(row * 128) +
                                (uint32_t)((seg ^ (row & 7)) << 4);
                ldsm_x4(a[i][0], a[i][1], a[i][2], a[i][3], addr);
            }
            uint32_t b[4][4];
#pragma unroll
            for (int p = 0; p < 4; ++p) {
                int row = wn * 64 + p * 16 + (lane & 7) + ((lane >> 4) << 3);
                int seg = kk * 2 + ((lane >> 3) & 1);
                uint32_t addr = bbuf + (uint32_t)(row * 128) +
                                (uint32_t)((seg ^ (row & 7)) << 4);
                ldsm_x4(b[p][0], b[p][1], b[p][2], b[p][3], addr);
            }
#pragma unroll
            for (int i = 0; i < 2; ++i)
#pragma unroll
                for (int p = 0; p < 4; ++p) {
                    mma16816(acc[i][p * 2],     a[i][0], a[i][1], a[i][2], a[i][3],
                             b[p][0], b[p][1]);
                    mma16816(acc[i][p * 2 + 1], a[i][0], a[i][1], a[i][2], a[i][3],
                             b[p][2], b[p][3]);
                }
        }
        __syncthreads();
        buf ^= 1;
    }

    // Epilogue: BN (+bias) and store fp32 to out[tb][d][n]
#pragma unroll
    for (int i = 0; i < 2; ++i) {
#pragma unroll
        for (int rr = 0; rr < 2; ++rr) {
            const int d = d0 + wm * 32 + i * 16 + (lane >> 2) + rr * 8;
            const float sc = gamma[d] * rsqrtf(var[d] + 1e-5f);
            float sh = beta[d] - mean[d] * sc;
            if (bias) sh = fmaf(sc, bias[d], sh);
            float* op = out + ((size_t)tb * C_ + d) * N_ + n0g + wn * 64 + (lane & 3) * 2;
#pragma unroll
            for (int p = 0; p < 8; ++p) {
                float2 o;
                o.x = fmaf(acc[i][p][rr * 2 + 0], sc, sh);
                o.y = fmaf(acc[i][p][rr * 2 + 1], sc, sh);
                *(float2*)(op + p * 8) = o;
            }
        }
    }
}

// ---------------------------------------------------------------------------
// Fused: q-LIF -> head-sum -> attn-LIF -> k-LIF -> yT (bf16, transposed)
// ---------------------------------------------------------------------------
__global__ void attn_fuse_kernel(const float* __restrict__ qlin,
                                 const float* __restrict__ klin,
                                 __nv_bfloat16* __restrict__ yT)
{
    const int bh = blockIdx.x;
    const int b  = bh >> 3;
    const int hd = bh & 7;
    const int n  = threadIdx.x;
    const size_t tstr = (size_t)BCN;

    float qs[4] = {0.f, 0.f, 0.f, 0.f};
    const size_t base = ((size_t)b * C_ + hd * CH) * N_ + n;

    for (int c = 0; c < CH; ++c) {
        const size_t idx = base + (size_t)c * N_;
        float v = 0.f;
#pragma unroll
        for (int t = 0; t < T_; ++t) {
            const float xq = qlin[idx + (size_t)t * tstr];
            const float h  = v + (xq - v) * 0.5f;
            const bool  sp = (h >= 1.0f);
            qs[t] += sp ? 1.f : 0.f;
            v = sp ? 0.f : h;
        }
    }

    float a[4];
    {
        float v = 0.f;
#pragma unroll
        for (int t = 0; t < T_; ++t) {
            const float h = v + (qs[t] - v) * 0.5f;
            const bool sp = (h >= 0.5f);
            a[t] = sp ? 1.f : 0.f;
            v = sp ? 0.f : h;
        }
    }

    for (int c = 0; c < CH; ++c) {
        const size_t idx = base + (size_t)c * N_;
        float v = 0.f;
#pragma unroll
        for (int t = 0; t < T_; ++t) {
            const float xk = klin[idx + (size_t)t * tstr];
            const float h  = v + (xk - v) * 0.5f;
            const bool  sp = (h >= 1.0f);
            const float yv = (sp ? 1.f : 0.f) * a[t];
            yT[((size_t)(t * B_ + b) * N_ + n) * C_ + hd * CH + c] = __float2bfloat16(yv);
            v = sp ? 0.f : h;
        }
    }
}

// ---------------------------------------------------------------------------
// Final LIF -> spikes to d_out
// ---------------------------------------------------------------------------
__global__ void final_lif_kernel(const float* __restrict__ p,
                                 float* __restrict__ o)
{
    const size_t i = (size_t)blockIdx.x * blockDim.x + threadIdx.x;
    float v = 0.f;
#pragma unroll
    for (int t = 0; t < T_; ++t) {
        const float x = p[i + (size_t)t * BCN];
        const float h = v + (x - v) * 0.5f;
        const bool sp = (h >= 1.0f);
        o[i + (size_t)t * BCN] = sp ? 1.f : 0.f;
        v = sp ? 0.f : h;
    }
}

// ---------------------------------------------------------------------------
extern "C" void kernel_launch(void* const* d_in, const int* in_sizes, int n_in,
                              void* d_out, int out_size)
{
    const float* x        = (const float*)d_in[0];
    const float* q_w      = (const float*)d_in[1];
    const float* q_gamma  = (const float*)d_in[2];
    const float* q_beta   = (const float*)d_in[3];
    const float* q_mean   = (const float*)d_in[4];
    const float* q_var    = (const float*)d_in[5];
    const float* k_w      = (const float*)d_in[6];
    const float* k_gamma  = (const float*)d_in[7];
    const float* k_beta   = (const float*)d_in[8];
    const float* k_mean   = (const float*)d_in[9];
    const float* k_var    = (const float*)d_in[10];
    const float* p_w      = (const float*)d_in[11];
    const float* p_gamma  = (const float*)d_in[12];
    const float* p_beta   = (const float*)d_in[13];
    const float* p_mean   = (const float*)d_in[14];
    const float* p_var    = (const float*)d_in[15];
    const float* p_b      = (const float*)d_in[16];

    float *qlin, *klin;
    __nv_bfloat16 *xs, *yT, *Aq, *Ak, *Ap;
    cudaGetSymbolAddress((void**)&qlin, g_qlin);
    cudaGetSymbolAddress((void**)&klin, g_klin);
    cudaGetSymbolAddress((void**)&xs, g_xs);
    cudaGetSymbolAddress((void**)&yT, g_yT);
    cudaGetSymbolAddress((void**)&Aq, g_Aq);
    cudaGetSymbolAddress((void**)&Ak, g_Ak);
    cudaGetSymbolAddress((void**)&Ap, g_Ap);

    cudaFuncSetAttribute(gemm_mma_kernel,
                         cudaFuncAttributeMaxDynamicSharedMemorySize, GSMEM);

    // prep
    split_w_kernel<<<(C_ * C_ + 255) / 256, 256>>>(q_w, Aq);
    split_w_kernel<<<(C_ * C_ + 255) / 256, 256>>>(k_w, Ak);
    split_w_kernel<<<(C_ * C_ + 255) / 256, 256>>>(p_w, Ap);
    split_x_kernel<<<dim3(N_ / 64, C_ / 64, TB_), 256>>>(x, xs);

    dim3 ggrid(2, 3, TB_);   // (nTiles, mTiles, tb)

    gemm_mma_kernel<<<ggrid, 256, GSMEM>>>(Aq, xs, 1,
                                           q_gamma, q_beta, q_mean, q_var,
                                           nullptr, qlin);
    gemm_mma_kernel<<<ggrid, 256, GSMEM>>>(Ak, xs, 1,
                                           k_gamma, k_beta, k_mean, k_var,
                                           nullptr, klin);

    attn_fuse_kernel<<<B_ * HEADS, N_>>>(qlin, klin, yT);

    gemm_mma_kernel<<<ggrid, 256, GSMEM>>>(Ap, yT, 0,
                                           p_gamma, p_beta, p_mean, p_var,
                                           p_b, qlin);

    final_lif_kernel<<<BCN / 256, 256>>>(qlin, (float*)d_out);
}

// round 7
// speedup vs baseline: 1.7741x; 1.1828x over previous
#include <cuda_runtime.h>
#include <cuda_bf16.h>
#include <cstdint>

// Problem constants
#define T_    4
#define B_    32
#define C_    384
#define N_    256
#define TB_   128
#define HEADS 8
#define CH    48
#define BCN   3145728
#define TBCN  12582912

// ------------------------- device global scratch ---------------------------
__device__ float g_qlin[TBCN];
__device__ float g_klin[TBCN];
__device__ __nv_bfloat16 g_xs[3u * TBCN];       // x splits, [3][tb][c][n]
__device__ __nv_bfloat16 g_y[TBCN];             // y, [tb][c][n] (tb = t*B+b)
__device__ __nv_bfloat16 g_Aq[C_ * 3 * C_];     // [d][3*384] W-split concat
__device__ __nv_bfloat16 g_Ak[C_ * 3 * C_];
__device__ __nv_bfloat16 g_Ap[C_ * 3 * C_];
__device__ float g_bnqk[4 * C_];                // scq, shq, sck, shk
__device__ float g_bnp[2 * C_];                 // scp, shp

// ------------------------- PTX helpers (generic sm_80+) --------------------
__device__ __forceinline__ uint32_t smem_to_u32(const void* p) {
    uint32_t a;
    asm("{ .reg .u64 t; cvta.to.shared.u64 t, %1; cvt.u32.u64 %0, t; }"
        : "=r"(a) : "l"(p));
    return a;
}
__device__ __forceinline__ void cp_async16(uint32_t dst, const void* src) {
    asm volatile("cp.async.cg.shared.global [%0], [%1], 16;"
                 :: "r"(dst), "l"(src));
}
__device__ __forceinline__ void ldsm_x4(uint32_t& r0, uint32_t& r1,
                                        uint32_t& r2, uint32_t& r3,
                                        uint32_t addr) {
    asm volatile("ldmatrix.sync.aligned.m8n8.x4.shared.b16 {%0,%1,%2,%3}, [%4];"
                 : "=r"(r0), "=r"(r1), "=r"(r2), "=r"(r3) : "r"(addr));
}
__device__ __forceinline__ void ldsm_x4_t(uint32_t& r0, uint32_t& r1,
                                          uint32_t& r2, uint32_t& r3,
                                          uint32_t addr) {
    asm volatile("ldmatrix.sync.aligned.m8n8.x4.trans.shared.b16 {%0,%1,%2,%3}, [%4];"
                 : "=r"(r0), "=r"(r1), "=r"(r2), "=r"(r3) : "r"(addr));
}
__device__ __forceinline__ void mma16816(float* d,
                                         uint32_t a0, uint32_t a1,
                                         uint32_t a2, uint32_t a3,
                                         uint32_t b0, uint32_t b1) {
    asm volatile(
        "mma.sync.aligned.m16n8k16.row.col.f32.bf16.bf16.f32 "
        "{%0,%1,%2,%3}, {%4,%5,%6,%7}, {%8,%9}, {%0,%1,%2,%3};"
        : "+f"(d[0]), "+f"(d[1]), "+f"(d[2]), "+f"(d[3])
        : "r"(a0), "r"(a1), "r"(a2), "r"(a3), "r"(b0), "r"(b1));
}

// ---------------------------------------------------------------------------
// prep kernels
// ---------------------------------------------------------------------------
__global__ void bn_prep_kernel(const float* __restrict__ g,
                               const float* __restrict__ b,
                               const float* __restrict__ m,
                               const float* __restrict__ v,
                               const float* __restrict__ bias,
                               float* __restrict__ sc,
                               float* __restrict__ sh)
{
    int d = threadIdx.x;
    if (d < C_) {
        float s = g[d] * rsqrtf(v[d] + 1e-5f);
        float t = b[d] - m[d] * s;
        if (bias) t = fmaf(s, bias[d], t);
        sc[d] = s;
        sh[d] = t;
    }
}

__global__ void split_w_kernel(const float* __restrict__ W,
                               __nv_bfloat16* __restrict__ A)
{
    int i = blockIdx.x * 256 + threadIdx.x;
    if (i >= C_ * C_) return;
    int d = i / C_, c = i % C_;
    float w = W[i];
    __nv_bfloat16 b1 = __float2bfloat16(w);
    float r = w - __bfloat162float(b1);
    __nv_bfloat16 b2 = __float2bfloat16(r);
    float r2 = r - __bfloat162float(b2);
    __nv_bfloat16 b3 = __float2bfloat16(r2);
    size_t base = (size_t)d * (3 * C_) + c;
    A[base]          = b1;
    A[base + C_]     = b2;
    A[base + 2 * C_] = b3;
}

// split x in-place layout (no transpose): xs[j][tb][c][n]
__global__ void split_x_kernel(const float* __restrict__ x,
                               __nv_bfloat16* __restrict__ xs)
{
    size_t i = ((size_t)blockIdx.x * 256 + threadIdx.x) * 4;
    float4 v = *(const float4*)(x + i);
    float vv[4] = {v.x, v.y, v.z, v.w};
    __nv_bfloat16 o1[4], o2[4], o3[4];
#pragma unroll
    for (int e = 0; e < 4; ++e) {
        __nv_bfloat16 b1 = __float2bfloat16(vv[e]);
        float r = vv[e] - __bfloat162float(b1);
        __nv_bfloat16 b2 = __float2bfloat16(r);
        float r2 = r - __bfloat162float(b2);
        o1[e] = b1; o2[e] = b2; o3[e] = __float2bfloat16(r2);
    }
    *(uint2*)(xs + i)                    = *(uint2*)o1;
    *(uint2*)(xs + (size_t)TBCN + i)     = *(uint2*)o2;
    *(uint2*)(xs + 2 * (size_t)TBCN + i) = *(uint2*)o3;
}

// ---------------------------------------------------------------------------
// HMMA GEMM + BN epilogue, exact bf16 split, B via ldmatrix.trans.
// CTA tile 128(d) x 128(n); BK=64; 8 warps (4m x 2n), warp tile 32x64.
// A: [384][1152] bf16 row-major; B: [c][n] native layout (xs or y).
// 3-stage cp.async pipeline, one __syncthreads per chunk.
// Dual mode: blockIdx.z in [0,256) -> z>>7 selects (Aq,outq) vs (Ak,outk).
// ---------------------------------------------------------------------------
#define STAGE_BYTES 32768
#define GSMEM       98304

__device__ __forceinline__ void gemm_load_chunk(const __nv_bfloat16* Ag,
                                                const __nv_bfloat16* Bg,
                                                uint32_t stage, int tid)
{
    uint32_t abuf = stage;
    uint32_t bbuf = stage + 16384;
#pragma unroll
    for (int q = 0; q < 4; ++q) {
        int idx = q * 256 + tid;
        int row = idx >> 3, seg = idx & 7;
        uint32_t off = (uint32_t)(row * 128) + (uint32_t)((seg ^ (row & 7)) << 4);
        cp_async16(abuf + off, (const char*)Ag + (size_t)row * 2304 + seg * 16);
    }
#pragma unroll
    for (int q = 0; q < 4; ++q) {
        int idx = q * 256 + tid;
        int row = idx >> 4, seg = idx & 15;
        uint32_t off = (uint32_t)(row * 256) + (uint32_t)((seg ^ (row & 7)) << 4);
        cp_async16(bbuf + off, (const char*)Bg + (size_t)row * 512 + seg * 16);
    }
}

__global__ __launch_bounds__(256, 2)
void gemm_mma_kernel(const __nv_bfloat16* __restrict__ Aq,
                     const __nv_bfloat16* __restrict__ Ak,
                     const __nv_bfloat16* __restrict__ Bx,
                     int nch,                       // 36 (6-term) or 18 (3-term)
                     const float* __restrict__ bn,  // [sel*2C : sc, sh]
                     float* __restrict__ outq,
                     float* __restrict__ outk)
{
    extern __shared__ char smem[];
    const uint32_t sbase = smem_to_u32(smem);
    const int tid  = threadIdx.x;
    const int wid  = tid >> 5;
    const int lane = tid & 31;
    const int nT = blockIdx.x, mT = blockIdx.y;
    const int sel = blockIdx.z >> 7;
    const int tb  = blockIdx.z & 127;
    const int d0  = mT * 128;
    const int n0g = nT * 128;
    const int wm = wid & 3;
    const int wn = wid >> 2;

    const __nv_bfloat16* A = sel ? Ak : Aq;
    float* out = sel ? outk : outq;
    const float* sc_arr = bn + sel * 2 * C_;
    const float* sh_arr = sc_arr + C_;

    // term map: kc -> (i, j, ksub)
    auto get_ptrs = [&](int kc, const __nv_bfloat16*& Ag, const __nv_bfloat16*& Bg) {
        const int t = kc / 6, ks = kc % 6;
        int i, j;
        if (nch == 36) {
            const int IM[6] = {0, 0, 1, 0, 1, 2};
            const int JM[6] = {0, 1, 0, 2, 1, 0};
            i = IM[t]; j = JM[t];
        } else { i = t; j = 0; }
        Ag = A + (size_t)d0 * 1152 + i * 384 + ks * 64;
        Bg = Bx + (size_t)j * TBCN + ((size_t)tb * C_ + ks * 64) * N_ + n0g;
    };

    float acc[2][8][4];
#pragma unroll
    for (int i = 0; i < 2; ++i)
#pragma unroll
        for (int p = 0; p < 8; ++p)
#pragma unroll
            for (int q = 0; q < 4; ++q) acc[i][p][q] = 0.f;

    // prologue: stages 0 and 1
    {
        const __nv_bfloat16 *Ag, *Bg;
        get_ptrs(0, Ag, Bg);
        gemm_load_chunk(Ag, Bg, sbase, tid);
        asm volatile("cp.async.commit_group;");
        get_ptrs(1, Ag, Bg);
        gemm_load_chunk(Ag, Bg, sbase + STAGE_BYTES, tid);
        asm volatile("cp.async.commit_group;");
    }

    for (int kc = 0; kc < nch; ++kc) {
        asm volatile("cp.async.wait_group 1;");
        __syncthreads();          // stage kc visible to all; slot (kc+2)%3 free

        if (kc + 2 < nch) {
            const __nv_bfloat16 *Ag, *Bg;
            get_ptrs(kc + 2, Ag, Bg);
            gemm_load_chunk(Ag, Bg, sbase + (uint32_t)((kc + 2) % 3) * STAGE_BYTES, tid);
        }
        asm volatile("cp.async.commit_group;");   // always commit (may be empty)

        const uint32_t abuf = sbase + (uint32_t)(kc % 3) * STAGE_BYTES;
        const uint32_t bbuf = abuf + 16384;

#pragma unroll
        for (int kk = 0; kk < 4; ++kk) {
            uint32_t a[2][4];
#pragma unroll
            for (int i = 0; i < 2; ++i) {
                int row = wm * 32 + i * 16 + (lane & 15);
                int seg = kk * 2 + (lane >> 4);
                uint32_t addr = abuf + (uint32_t)(row * 128) +
                                (uint32_t)((seg ^ (row & 7)) << 4);
                ldsm_x4(a[i][0], a[i][1], a[i][2], a[i][3], addr);
            }
            uint32_t b[4][4];
#pragma unroll
            for (int p = 0; p < 4; ++p) {
                // trans load from [c][n] tile: row = k, seg = n/8
                int krow = kk * 16 + ((lane >> 3) & 1) * 8 + (lane & 7);
                int seg  = wn * 8 + p * 2 + (lane >> 4);
                uint32_t addr = bbuf + (uint32_t)(krow * 256) +
                                (uint32_t)((seg ^ (krow & 7)) << 4);
                ldsm_x4_t(b[p][0], b[p][1], b[p][2], b[p][3], addr);
            }
#pragma unroll
            for (int i = 0; i < 2; ++i)
#pragma unroll
                for (int p = 0; p < 4; ++p) {
                    mma16816(acc[i][p * 2],     a[i][0], a[i][1], a[i][2], a[i][3],
                             b[p][0], b[p][1]);
                    mma16816(acc[i][p * 2 + 1], a[i][0], a[i][1], a[i][2], a[i][3],
                             b[p][2], b[p][3]);
                }
        }
    }

    // Epilogue: BN and store fp32 to out[tb][d][n]
#pragma unroll
    for (int i = 0; i < 2; ++i) {
#pragma unroll
        for (int rr = 0; rr < 2; ++rr) {
            const int d = d0 + wm * 32 + i * 16 + (lane >> 2) + rr * 8;
            const float sc = sc_arr[d];
            const float sh = sh_arr[d];
            float* op = out + ((size_t)tb * C_ + d) * N_ + n0g + wn * 64 + (lane & 3) * 2;
#pragma unroll
            for (int p = 0; p < 8; ++p) {
                float2 o;
                o.x = fmaf(acc[i][p][rr * 2 + 0], sc, sh);
                o.y = fmaf(acc[i][p][rr * 2 + 1], sc, sh);
                *(float2*)(op + p * 8) = o;
            }
        }
    }
}

// ---------------------------------------------------------------------------
// Fused: q-LIF -> head-sum -> attn-LIF -> k-LIF -> y (bf16, native layout)
// ---------------------------------------------------------------------------
__global__ void attn_fuse_kernel(const float* __restrict__ qlin,
                                 const float* __restrict__ klin,
                                 __nv_bfloat16* __restrict__ y)
{
    const int bh = blockIdx.x;
    const int b  = bh >> 3;
    const int hd = bh & 7;
    const int n  = threadIdx.x;
    const size_t tstr = (size_t)BCN;

    float qs[4] = {0.f, 0.f, 0.f, 0.f};
    const size_t base = ((size_t)b * C_ + hd * CH) * N_ + n;

    for (int c = 0; c < CH; ++c) {
        const size_t idx = base + (size_t)c * N_;
        float v = 0.f;
#pragma unroll
        for (int t = 0; t < T_; ++t) {
            const float xq = qlin[idx + (size_t)t * tstr];
            const float h  = v + (xq - v) * 0.5f;
            const bool  sp = (h >= 1.0f);
            qs[t] += sp ? 1.f : 0.f;
            v = sp ? 0.f : h;
        }
    }

    float a[4];
    {
        float v = 0.f;
#pragma unroll
        for (int t = 0; t < T_; ++t) {
            const float h = v + (qs[t] - v) * 0.5f;
            const bool sp = (h >= 0.5f);
            a[t] = sp ? 1.f : 0.f;
            v = sp ? 0.f : h;
        }
    }

    for (int c = 0; c < CH; ++c) {
        const size_t idx = base + (size_t)c * N_;
        float v = 0.f;
#pragma unroll
        for (int t = 0; t < T_; ++t) {
            const float xk = klin[idx + (size_t)t * tstr];
            const float h  = v + (xk - v) * 0.5f;
            const bool  sp = (h >= 1.0f);
            const float yv = (sp ? 1.f : 0.f) * a[t];
            y[idx + (size_t)t * tstr] = __float2bfloat16(yv);   // coalesced over n
            v = sp ? 0.f : h;
        }
    }
}

// ---------------------------------------------------------------------------
// Final LIF -> spikes to d_out
// ---------------------------------------------------------------------------
__global__ void final_lif_kernel(const float* __restrict__ p,
                                 float* __restrict__ o)
{
    const size_t i = (size_t)blockIdx.x * blockDim.x + threadIdx.x;
    float v = 0.f;
#pragma unroll
    for (int t = 0; t < T_; ++t) {
        const float x = p[i + (size_t)t * BCN];
        const float h = v + (x - v) * 0.5f;
        const bool sp = (h >= 1.0f);
        o[i + (size_t)t * BCN] = sp ? 1.f : 0.f;
        v = sp ? 0.f : h;
    }
}

// ---------------------------------------------------------------------------
extern "C" void kernel_launch(void* const* d_in, const int* in_sizes, int n_in,
                              void* d_out, int out_size)
{
    const float* x        = (const float*)d_in[0];
    const float* q_w      = (const float*)d_in[1];
    const float* q_gamma  = (const float*)d_in[2];
    const float* q_beta   = (const float*)d_in[3];
    const float* q_mean   = (const float*)d_in[4];
    const float* q_var    = (const float*)d_in[5];
    const float* k_w      = (const float*)d_in[6];
    const float* k_gamma  = (const float*)d_in[7];
    const float* k_beta   = (const float*)d_in[8];
    const float* k_mean   = (const float*)d_in[9];
    const float* k_var    = (const float*)d_in[10];
    const float* p_w      = (const float*)d_in[11];
    const float* p_gamma  = (const float*)d_in[12];
    const float* p_beta   = (const float*)d_in[13];
    const float* p_mean   = (const float*)d_in[14];
    const float* p_var    = (const float*)d_in[15];
    const float* p_b      = (const float*)d_in[16];

    float *qlin, *klin, *bnqk, *bnp;
    __nv_bfloat16 *xs, *y, *Aq, *Ak, *Ap;
    cudaGetSymbolAddress((void**)&qlin, g_qlin);
    cudaGetSymbolAddress((void**)&klin, g_klin);
    cudaGetSymbolAddress((void**)&xs, g_xs);
    cudaGetSymbolAddress((void**)&y, g_y);
    cudaGetSymbolAddress((void**)&Aq, g_Aq);
    cudaGetSymbolAddress((void**)&Ak, g_Ak);
    cudaGetSymbolAddress((void**)&Ap, g_Ap);
    cudaGetSymbolAddress((void**)&bnqk, g_bnqk);
    cudaGetSymbolAddress((void**)&bnp, g_bnp);

    cudaFuncSetAttribute(gemm_mma_kernel,
                         cudaFuncAttributeMaxDynamicSharedMemorySize, GSMEM);

    // prep
    bn_prep_kernel<<<1, C_>>>(q_gamma, q_beta, q_mean, q_var, nullptr,
                              bnqk, bnqk + C_);
    bn_prep_kernel<<<1, C_>>>(k_gamma, k_beta, k_mean, k_var, nullptr,
                              bnqk + 2 * C_, bnqk + 3 * C_);
    bn_prep_kernel<<<1, C_>>>(p_gamma, p_beta, p_mean, p_var, p_b,
                              bnp, bnp + C_);
    split_w_kernel<<<(C_ * C_ + 255) / 256, 256>>>(q_w, Aq);
    split_w_kernel<<<(C_ * C_ + 255) / 256, 256>>>(k_w, Ak);
    split_w_kernel<<<(C_ * C_ + 255) / 256, 256>>>(p_w, Ap);
    split_x_kernel<<<TBCN / 1024, 256>>>(x, xs);

    // merged q+k GEMM (6-term exact split each)
    gemm_mma_kernel<<<dim3(2, 3, 256), 256, GSMEM>>>(Aq, Ak, xs, 36,
                                                     bnqk, qlin, klin);

    attn_fuse_kernel<<<B_ * HEADS, N_>>>(qlin, klin, y);

    // proj GEMM (3-term: y exact in bf16)
    gemm_mma_kernel<<<dim3(2, 3, 128), 256, GSMEM>>>(Ap, Ap, y, 18,
                                                     bnp, qlin, qlin);

    final_lif_kernel<<<BCN / 256, 256>>>(qlin, (float*)d_out);
}

// round 8
// speedup vs baseline: 1.8277x; 1.0303x over previous
#include <cuda_runtime.h>
#include <cuda_bf16.h>
#include <cstdint>

// Problem constants
#define T_    4
#define B_    32
#define C_    384
#define N_    256
#define TB_   128
#define HEADS 8
#define CH    48
#define BCN   3145728
#define TBCN  12582912

// ------------------------- device global scratch ---------------------------
__device__ float g_qlin[TBCN];
__device__ float g_klin[TBCN];
__device__ __nv_bfloat16 g_xs[3u * TBCN];       // x splits, [3][tb][c][n]
__device__ __nv_bfloat16 g_y[TBCN];             // y, [tb][c][n]
__device__ __nv_bfloat16 g_Aq[C_ * 3 * C_];     // [d][3*384] W-split concat
__device__ __nv_bfloat16 g_Ak[C_ * 3 * C_];
__device__ __nv_bfloat16 g_Ap[C_ * 3 * C_];
__device__ float g_bnqk[4 * C_];                // scq, shq, sck, shk
__device__ float g_bnp[2 * C_];                 // scp, shp

// ------------------------- PTX helpers (generic sm_80+) --------------------
__device__ __forceinline__ uint32_t smem_to_u32(const void* p) {
    uint32_t a;
    asm("{ .reg .u64 t; cvta.to.shared.u64 t, %1; cvt.u32.u64 %0, t; }"
        : "=r"(a) : "l"(p));
    return a;
}
__device__ __forceinline__ void cp_async16(uint32_t dst, const void* src) {
    asm volatile("cp.async.cg.shared.global [%0], [%1], 16;"
                 :: "r"(dst), "l"(src));
}
__device__ __forceinline__ void ldsm_x4(uint32_t& r0, uint32_t& r1,
                                        uint32_t& r2, uint32_t& r3,
                                        uint32_t addr) {
    asm volatile("ldmatrix.sync.aligned.m8n8.x4.shared.b16 {%0,%1,%2,%3}, [%4];"
                 : "=r"(r0), "=r"(r1), "=r"(r2), "=r"(r3) : "r"(addr));
}
__device__ __forceinline__ void ldsm_x4_t(uint32_t& r0, uint32_t& r1,
                                          uint32_t& r2, uint32_t& r3,
                                          uint32_t addr) {
    asm volatile("ldmatrix.sync.aligned.m8n8.x4.trans.shared.b16 {%0,%1,%2,%3}, [%4];"
                 : "=r"(r0), "=r"(r1), "=r"(r2), "=r"(r3) : "r"(addr));
}
__device__ __forceinline__ void mma16816(float* d,
                                         uint32_t a0, uint32_t a1,
                                         uint32_t a2, uint32_t a3,
                                         uint32_t b0, uint32_t b1) {
    asm volatile(
        "mma.sync.aligned.m16n8k16.row.col.f32.bf16.bf16.f32 "
        "{%0,%1,%2,%3}, {%4,%5,%6,%7}, {%8,%9}, {%0,%1,%2,%3};"
        : "+f"(d[0]), "+f"(d[1]), "+f"(d[2]), "+f"(d[3])
        : "r"(a0), "r"(a1), "r"(a2), "r"(a3), "r"(b0), "r"(b1));
}

// ---------------------------------------------------------------------------
// prep kernels (merged launches)
// ---------------------------------------------------------------------------
__global__ void bn_prep_all_kernel(const float* __restrict__ qg, const float* __restrict__ qb,
                                   const float* __restrict__ qm, const float* __restrict__ qv,
                                   const float* __restrict__ kg, const float* __restrict__ kb,
                                   const float* __restrict__ km, const float* __restrict__ kv,
                                   const float* __restrict__ pg, const float* __restrict__ pb,
                                   const float* __restrict__ pm, const float* __restrict__ pv,
                                   const float* __restrict__ pbias,
                                   float* __restrict__ bnqk, float* __restrict__ bnp)
{
    int d = threadIdx.x;
    if (d >= C_) return;
    if (blockIdx.x == 0) {
        float s = qg[d] * rsqrtf(qv[d] + 1e-5f);
        bnqk[d]      = s;
        bnqk[C_ + d] = qb[d] - qm[d] * s;
    } else if (blockIdx.x == 1) {
        float s = kg[d] * rsqrtf(kv[d] + 1e-5f);
        bnqk[2 * C_ + d] = s;
        bnqk[3 * C_ + d] = kb[d] - km[d] * s;
    } else {
        float s = pg[d] * rsqrtf(pv[d] + 1e-5f);
        bnp[d]      = s;
        bnp[C_ + d] = fmaf(s, pbias[d], pb[d] - pm[d] * s);
    }
}

__global__ void split_w_all_kernel(const float* __restrict__ Wq,
                                   const float* __restrict__ Wk,
                                   const float* __restrict__ Wp,
                                   __nv_bfloat16* __restrict__ Aq,
                                   __nv_bfloat16* __restrict__ Ak,
                                   __nv_bfloat16* __restrict__ Ap)
{
    int i = blockIdx.x * 256 + threadIdx.x;
    if (i >= C_ * C_) return;
    const float* W = (blockIdx.y == 0) ? Wq : (blockIdx.y == 1) ? Wk : Wp;
    __nv_bfloat16* A = (blockIdx.y == 0) ? Aq : (blockIdx.y == 1) ? Ak : Ap;
    int d = i / C_, c = i % C_;
    float w = W[i];
    __nv_bfloat16 b1 = __float2bfloat16(w);
    float r = w - __bfloat162float(b1);
    __nv_bfloat16 b2 = __float2bfloat16(r);
    float r2 = r - __bfloat162float(b2);
    __nv_bfloat16 b3 = __float2bfloat16(r2);
    size_t base = (size_t)d * (3 * C_) + c;
    A[base]          = b1;
    A[base + C_]     = b2;
    A[base + 2 * C_] = b3;
}

__global__ void split_x_kernel(const float* __restrict__ x,
                               __nv_bfloat16* __restrict__ xs)
{
    size_t i = ((size_t)blockIdx.x * 256 + threadIdx.x) * 4;
    float4 v = *(const float4*)(x + i);
    float vv[4] = {v.x, v.y, v.z, v.w};
    __nv_bfloat16 o1[4], o2[4], o3[4];
#pragma unroll
    for (int e = 0; e < 4; ++e) {
        __nv_bfloat16 b1 = __float2bfloat16(vv[e]);
        float r = vv[e] - __bfloat162float(b1);
        __nv_bfloat16 b2 = __float2bfloat16(r);
        float r2 = r - __bfloat162float(b2);
        o1[e] = b1; o2[e] = b2; o3[e] = __float2bfloat16(r2);
    }
    *(uint2*)(xs + i)                    = *(uint2*)o1;
    *(uint2*)(xs + (size_t)TBCN + i)     = *(uint2*)o2;
    *(uint2*)(xs + 2 * (size_t)TBCN + i) = *(uint2*)o3;
}

// ---------------------------------------------------------------------------
// DUAL-output HMMA GEMM for q+k: one CTA computes both q and k 128x128 tiles,
// sharing the B (x-split) tile.  512 threads, 16 warps (8m x 2n), warp tile
// 16(m) x 64(n) per output.  3-stage cp.async pipeline.
// Stage layout: [Aq 16KB][Ak 16KB][B 16KB] = 48KB; 3 stages = 144KB smem.
// ---------------------------------------------------------------------------
#define DSTAGE 49152
#define DSMEM  147456

__constant__ int c_IM[6] = {0, 0, 1, 0, 1, 2};
__constant__ int c_JM[6] = {0, 1, 0, 2, 1, 0};

__device__ __forceinline__ void dual_load_chunk(const __nv_bfloat16* __restrict__ Aq,
                                                const __nv_bfloat16* __restrict__ Ak,
                                                const __nv_bfloat16* __restrict__ Bx,
                                                int d0, int n0g, int tb, int kc,
                                                uint32_t stage, int tid)
{
    const int t = kc / 6, ks = kc % 6;
    const int i = c_IM[t], j = c_JM[t];
    const char* AgQ = (const char*)(Aq + (size_t)d0 * 1152 + i * 384 + ks * 64);
    const char* AgK = (const char*)(Ak + (size_t)d0 * 1152 + i * 384 + ks * 64);
    const char* Bg  = (const char*)(Bx + (size_t)j * TBCN +
                                    ((size_t)tb * C_ + ks * 64) * N_ + n0g);
#pragma unroll
    for (int q = 0; q < 2; ++q) {
        int idx = q * 512 + tid;
        int row = idx >> 3, seg = idx & 7;
        uint32_t off = (uint32_t)(row * 128) + (uint32_t)((seg ^ (row & 7)) << 4);
        cp_async16(stage + off,         AgQ + (size_t)row * 2304 + seg * 16);
        cp_async16(stage + 16384 + off, AgK + (size_t)row * 2304 + seg * 16);
    }
#pragma unroll
    for (int q = 0; q < 2; ++q) {
        int idx = q * 512 + tid;
        int row = idx >> 4, seg = idx & 15;
        uint32_t off = (uint32_t)(row * 256) + (uint32_t)((seg ^ (row & 7)) << 4);
        cp_async16(stage + 32768 + off, Bg + (size_t)row * 512 + seg * 16);
    }
}

__global__ __launch_bounds__(512, 1)
void gemm_qk_dual_kernel(const __nv_bfloat16* __restrict__ Aq,
                         const __nv_bfloat16* __restrict__ Ak,
                         const __nv_bfloat16* __restrict__ Bx,
                         const float* __restrict__ bn,
                         float* __restrict__ outq,
                         float* __restrict__ outk)
{
    extern __shared__ char smem[];
    const uint32_t sbase = smem_to_u32(smem);
    const int tid  = threadIdx.x;
    const int wid  = tid >> 5;
    const int lane = tid & 31;
    const int nT = blockIdx.x, mT = blockIdx.y, tb = blockIdx.z;
    const int d0  = mT * 128;
    const int n0g = nT * 128;
    const int wm = wid & 7;      // 8 m-warps x 16 rows
    const int wn = wid >> 3;     // 2 n-warps x 64 cols
    const int nch = 36;

    float accq[8][4], acck[8][4];
#pragma unroll
    for (int p = 0; p < 8; ++p)
#pragma unroll
        for (int q = 0; q < 4; ++q) { accq[p][q] = 0.f; acck[p][q] = 0.f; }

    dual_load_chunk(Aq, Ak, Bx, d0, n0g, tb, 0, sbase, tid);
    asm volatile("cp.async.commit_group;");
    dual_load_chunk(Aq, Ak, Bx, d0, n0g, tb, 1, sbase + DSTAGE, tid);
    asm volatile("cp.async.commit_group;");

    for (int kc = 0; kc < nch; ++kc) {
        asm volatile("cp.async.wait_group 1;");
        __syncthreads();

        if (kc + 2 < nch)
            dual_load_chunk(Aq, Ak, Bx, d0, n0g, tb, kc + 2,
                            sbase + (uint32_t)((kc + 2) % 3) * DSTAGE, tid);
        asm volatile("cp.async.commit_group;");

        const uint32_t aqb = sbase + (uint32_t)(kc % 3) * DSTAGE;
        const uint32_t akb = aqb + 16384;
        const uint32_t bbf = aqb + 32768;

#pragma unroll
        for (int kk = 0; kk < 4; ++kk) {
            uint32_t aq[4], ak[4];
            {
                int row = wm * 16 + (lane & 15);
                int seg = kk * 2 + (lane >> 4);
                uint32_t aoff = (uint32_t)(row * 128) + (uint32_t)((seg ^ (row & 7)) << 4);
                ldsm_x4(aq[0], aq[1], aq[2], aq[3], aqb + aoff);
                ldsm_x4(ak[0], ak[1], ak[2], ak[3], akb + aoff);
            }
            uint32_t b[4][4];
#pragma unroll
            for (int p = 0; p < 4; ++p) {
                int krow = kk * 16 + ((lane >> 3) & 1) * 8 + (lane & 7);
                int seg  = wn * 8 + p * 2 + (lane >> 4);
                uint32_t addr = bbf + (uint32_t)(krow * 256) +
                                (uint32_t)((seg ^ (krow & 7)) << 4);
                ldsm_x4_t(b[p][0], b[p][1], b[p][2], b[p][3], addr);
            }
#pragma unroll
            for (int p = 0; p < 4; ++p) {
                mma16816(accq[p * 2],     aq[0], aq[1], aq[2], aq[3], b[p][0], b[p][1]);
                mma16816(accq[p * 2 + 1], aq[0], aq[1], aq[2], aq[3], b[p][2], b[p][3]);
                mma16816(acck[p * 2],     ak[0], ak[1], ak[2], ak[3], b[p][0], b[p][1]);
                mma16816(acck[p * 2 + 1], ak[0], ak[1], ak[2], ak[3], b[p][2], b[p][3]);
            }
        }
    }

    // Epilogue: BN, store both outputs
#pragma unroll
    for (int rr = 0; rr < 2; ++rr) {
        const int d = d0 + wm * 16 + (lane >> 2) + rr * 8;
        const float scq = bn[d],          shq = bn[C_ + d];
        const float sck = bn[2 * C_ + d], shk = bn[3 * C_ + d];
        float* opq = outq + ((size_t)tb * C_ + d) * N_ + n0g + wn * 64 + (lane & 3) * 2;
        float* opk = outk + ((size_t)tb * C_ + d) * N_ + n0g + wn * 64 + (lane & 3) * 2;
#pragma unroll
        for (int j = 0; j < 8; ++j) {
            float2 oq, ok;
            oq.x = fmaf(accq[j][rr * 2 + 0], scq, shq);
            oq.y = fmaf(accq[j][rr * 2 + 1], scq, shq);
            ok.x = fmaf(acck[j][rr * 2 + 0], sck, shk);
            ok.y = fmaf(acck[j][rr * 2 + 1], sck, shk);
            *(float2*)(opq + j * 8) = oq;
            *(float2*)(opk + j * 8) = ok;
        }
    }
}

// ---------------------------------------------------------------------------
// Single-output HMMA GEMM (proj): R7 kernel, 3-term split, 18 chunks.
// ---------------------------------------------------------------------------
#define STAGE_BYTES 32768
#define GSMEM       98304

__device__ __forceinline__ void gemm_load_chunk(const __nv_bfloat16* Ag,
                                                const __nv_bfloat16* Bg,
                                                uint32_t stage, int tid)
{
    uint32_t abuf = stage;
    uint32_t bbuf = stage + 16384;
#pragma unroll
    for (int q = 0; q < 4; ++q) {
        int idx = q * 256 + tid;
        int row = idx >> 3, seg = idx & 7;
        uint32_t off = (uint32_t)(row * 128) + (uint32_t)((seg ^ (row & 7)) << 4);
        cp_async16(abuf + off, (const char*)Ag + (size_t)row * 2304 + seg * 16);
    }
#pragma unroll
    for (int q = 0; q < 4; ++q) {
        int idx = q * 256 + tid;
        int row = idx >> 4, seg = idx & 15;
        uint32_t off = (uint32_t)(row * 256) + (uint32_t)((seg ^ (row & 7)) << 4);
        cp_async16(bbuf + off, (const char*)Bg + (size_t)row * 512 + seg * 16);
    }
}

__global__ __launch_bounds__(256, 2)
void gemm_mma_kernel(const __nv_bfloat16* __restrict__ A,
                     const __nv_bfloat16* __restrict__ Bx,
                     const float* __restrict__ bn,
                     float* __restrict__ out)
{
    extern __shared__ char smem[];
    const uint32_t sbase = smem_to_u32(smem);
    const int tid  = threadIdx.x;
    const int wid  = tid >> 5;
    const int lane = tid & 31;
    const int nT = blockIdx.x, mT = blockIdx.y, tb = blockIdx.z;
    const int d0  = mT * 128;
    const int n0g = nT * 128;
    const int wm = wid & 3;
    const int wn = wid >> 2;
    const int nch = 18;

    auto get_ptrs = [&](int kc, const __nv_bfloat16*& Ag, const __nv_bfloat16*& Bg) {
        const int t = kc / 6, ks = kc % 6;
        Ag = A + (size_t)d0 * 1152 + t * 384 + ks * 64;
        Bg = Bx + ((size_t)tb * C_ + ks * 64) * N_ + n0g;
    };

    float acc[2][8][4];
#pragma unroll
    for (int i = 0; i < 2; ++i)
#pragma unroll
        for (int p = 0; p < 8; ++p)
#pragma unroll
            for (int q = 0; q < 4; ++q) acc[i][p][q] = 0.f;

    {
        const __nv_bfloat16 *Ag, *Bg;
        get_ptrs(0, Ag, Bg);
        gemm_load_chunk(Ag, Bg, sbase, tid);
        asm volatile("cp.async.commit_group;");
        get_ptrs(1, Ag, Bg);
        gemm_load_chunk(Ag, Bg, sbase + STAGE_BYTES, tid);
        asm volatile("cp.async.commit_group;");
    }

    for (int kc = 0; kc < nch; ++kc) {
        asm volatile("cp.async.wait_group 1;");
        __syncthreads();

        if (kc + 2 < nch) {
            const __nv_bfloat16 *Ag, *Bg;
            get_ptrs(kc + 2, Ag, Bg);
            gemm_load_chunk(Ag, Bg, sbase + (uint32_t)((kc + 2) % 3) * STAGE_BYTES, tid);
        }
        asm volatile("cp.async.commit_group;");

        const uint32_t abuf = sbase + (uint32_t)(kc % 3) * STAGE_BYTES;
        const uint32_t bbuf = abuf + 16384;

#pragma unroll
        for (int kk = 0; kk < 4; ++kk) {
            uint32_t a[2][4];
#pragma unroll
            for (int i = 0; i < 2; ++i) {
                int row = wm * 32 + i * 16 + (lane & 15);
                int seg = kk * 2 + (lane >> 4);
                uint32_t addr = abuf + (uint32_t)(row * 128) +
                                (uint32_t)((seg ^ (row & 7)) << 4);
                ldsm_x4(a[i][0], a[i][1], a[i][2], a[i][3], addr);
            }
            uint32_t b[4][4];
#pragma unroll
            for (int p = 0; p < 4; ++p) {
                int krow = kk * 16 + ((lane >> 3) & 1) * 8 + (lane & 7);
                int seg  = wn * 8 + p * 2 + (lane >> 4);
                uint32_t addr = bbuf + (uint32_t)(krow * 256) +
                                (uint32_t)((seg ^ (krow & 7)) << 4);
                ldsm_x4_t(b[p][0], b[p][1], b[p][2], b[p][3], addr);
            }
#pragma unroll
            for (int i = 0; i < 2; ++i)
#pragma unroll
                for (int p = 0; p < 4; ++p) {
                    mma16816(acc[i][p * 2],     a[i][0], a[i][1], a[i][2], a[i][3],
                             b[p][0], b[p][1]);
                    mma16816(acc[i][p * 2 + 1], a[i][0], a[i][1], a[i][2], a[i][3],
                             b[p][2], b[p][3]);
                }
        }
    }

#pragma unroll
    for (int i = 0; i < 2; ++i) {
#pragma unroll
        for (int rr = 0; rr < 2; ++rr) {
            const int d = d0 + wm * 32 + i * 16 + (lane >> 2) + rr * 8;
            const float sc = bn[d];
            const float sh = bn[C_ + d];
            float* op = out + ((size_t)tb * C_ + d) * N_ + n0g + wn * 64 + (lane & 3) * 2;
#pragma unroll
            for (int p = 0; p < 8; ++p) {
                float2 o;
                o.x = fmaf(acc[i][p][rr * 2 + 0], sc, sh);
                o.y = fmaf(acc[i][p][rr * 2 + 1], sc, sh);
                *(float2*)(op + p * 8) = o;
            }
        }
    }
}

// ---------------------------------------------------------------------------
// Fused: q-LIF -> head-sum -> attn-LIF -> k-LIF -> y (bf16)
// ---------------------------------------------------------------------------
__global__ void attn_fuse_kernel(const float* __restrict__ qlin,
                                 const float* __restrict__ klin,
                                 __nv_bfloat16* __restrict__ y)
{
    const int bh = blockIdx.x;
    const int b  = bh >> 3;
    const int hd = bh & 7;
    const int n  = threadIdx.x;
    const size_t tstr = (size_t)BCN;

    float qs[4] = {0.f, 0.f, 0.f, 0.f};
    const size_t base = ((size_t)b * C_ + hd * CH) * N_ + n;

    for (int c = 0; c < CH; ++c) {
        const size_t idx = base + (size_t)c * N_;
        float v = 0.f;
#pragma unroll
        for (int t = 0; t < T_; ++t) {
            const float xq = qlin[idx + (size_t)t * tstr];
            const float h  = v + (xq - v) * 0.5f;
            const bool  sp = (h >= 1.0f);
            qs[t] += sp ? 1.f : 0.f;
            v = sp ? 0.f : h;
        }
    }

    float a[4];
    {
        float v = 0.f;
#pragma unroll
        for (int t = 0; t < T_; ++t) {
            const float h = v + (qs[t] - v) * 0.5f;
            const bool sp = (h >= 0.5f);
            a[t] = sp ? 1.f : 0.f;
            v = sp ? 0.f : h;
        }
    }

    for (int c = 0; c < CH; ++c) {
        const size_t idx = base + (size_t)c * N_;
        float v = 0.f;
#pragma unroll
        for (int t = 0; t < T_; ++t) {
            const float xk = klin[idx + (size_t)t * tstr];
            const float h  = v + (xk - v) * 0.5f;
            const bool  sp = (h >= 1.0f);
            const float yv = (sp ? 1.f : 0.f) * a[t];
            y[idx + (size_t)t * tstr] = __float2bfloat16(yv);
            v = sp ? 0.f : h;
        }
    }
}

// ---------------------------------------------------------------------------
// Final LIF -> spikes to d_out
// ---------------------------------------------------------------------------
__global__ void final_lif_kernel(const float* __restrict__ p,
                                 float* __restrict__ o)
{
    const size_t i = (size_t)blockIdx.x * blockDim.x + threadIdx.x;
    float v = 0.f;
#pragma unroll
    for (int t = 0; t < T_; ++t) {
        const float x = p[i + (size_t)t * BCN];
        const float h = v + (x - v) * 0.5f;
        const bool sp = (h >= 1.0f);
        o[i + (size_t)t * BCN] = sp ? 1.f : 0.f;
        v = sp ? 0.f : h;
    }
}

// ---------------------------------------------------------------------------
extern "C" void kernel_launch(void* const* d_in, const int* in_sizes, int n_in,
                              void* d_out, int out_size)
{
    const float* x        = (const float*)d_in[0];
    const float* q_w      = (const float*)d_in[1];
    const float* q_gamma  = (const float*)d_in[2];
    const float* q_beta   = (const float*)d_in[3];
    const float* q_mean   = (const float*)d_in[4];
    const float* q_var    = (const float*)d_in[5];
    const float* k_w      = (const float*)d_in[6];
    const float* k_gamma  = (const float*)d_in[7];
    const float* k_beta   = (const float*)d_in[8];
    const float* k_mean   = (const float*)d_in[9];
    const float* k_var    = (const float*)d_in[10];
    const float* p_w      = (const float*)d_in[11];
    const float* p_gamma  = (const float*)d_in[12];
    const float* p_beta   = (const float*)d_in[13];
    const float* p_mean   = (const float*)d_in[14];
    const float* p_var    = (const float*)d_in[15];
    const float* p_b      = (const float*)d_in[16];

    float *qlin, *klin, *bnqk, *bnp;
    __nv_bfloat16 *xs, *y, *Aq, *Ak, *Ap;
    cudaGetSymbolAddress((void**)&qlin, g_qlin);
    cudaGetSymbolAddress((void**)&klin, g_klin);
    cudaGetSymbolAddress((void**)&xs, g_xs);
    cudaGetSymbolAddress((void**)&y, g_y);
    cudaGetSymbolAddress((void**)&Aq, g_Aq);
    cudaGetSymbolAddress((void**)&Ak, g_Ak);
    cudaGetSymbolAddress((void**)&Ap, g_Ap);
    cudaGetSymbolAddress((void**)&bnqk, g_bnqk);
    cudaGetSymbolAddress((void**)&bnp, g_bnp);

    cudaFuncSetAttribute(gemm_qk_dual_kernel,
                         cudaFuncAttributeMaxDynamicSharedMemorySize, DSMEM);
    cudaFuncSetAttribute(gemm_mma_kernel,
                         cudaFuncAttributeMaxDynamicSharedMemorySize, GSMEM);

    // prep (merged: 3 launches)
    bn_prep_all_kernel<<<3, C_>>>(q_gamma, q_beta, q_mean, q_var,
                                  k_gamma, k_beta, k_mean, k_var,
                                  p_gamma, p_beta, p_mean, p_var, p_b,
                                  bnqk, bnp);
    split_w_all_kernel<<<dim3((C_ * C_ + 255) / 256, 3), 256>>>(q_w, k_w, p_w,
                                                                Aq, Ak, Ap);
    split_x_kernel<<<TBCN / 1024, 256>>>(x, xs);

    // dual q+k GEMM (shared B)
    gemm_qk_dual_kernel<<<dim3(2, 3, 128), 512, DSMEM>>>(Aq, Ak, xs, bnqk,
                                                         qlin, klin);

    attn_fuse_kernel<<<B_ * HEADS, N_>>>(qlin, klin, y);

    // proj GEMM (3-term)
    gemm_mma_kernel<<<dim3(2, 3, 128), 256, GSMEM>>>(Ap, y, bnp, qlin);

    final_lif_kernel<<<BCN / 256, 256>>>(qlin, (float*)d_out);
}

// round 9
// speedup vs baseline: 2.0293x; 1.1103x over previous
#include <cuda_runtime.h>
#include <cuda_bf16.h>
#include <cstdint>

// Problem constants
#define T_    4
#define B_    32
#define C_    384
#define N_    256
#define TB_   128
#define HEADS 8
#define CH    48
#define BCN   3145728
#define TBCN  12582912

// ------------------------- device global scratch ---------------------------
__device__ float g_qlin[TBCN];
__device__ float g_klin[TBCN];
__device__ __nv_bfloat16 g_xs[3u * TBCN];       // x splits, [3][tb][c][n]
__device__ __nv_bfloat16 g_y[TBCN];             // y, [tb][c][n]
__device__ __nv_bfloat16 g_Aq[C_ * 3 * C_];     // [d][3*384] W-split concat
__device__ __nv_bfloat16 g_Ak[C_ * 3 * C_];
__device__ __nv_bfloat16 g_Ap[C_ * 3 * C_];
__device__ float g_bnqk[4 * C_];                // scq, shq, sck, shk
__device__ float g_bnp[2 * C_];                 // scp, shp

// ------------------------- PTX helpers (generic sm_80+) --------------------
__device__ __forceinline__ uint32_t smem_to_u32(const void* p) {
    uint32_t a;
    asm("{ .reg .u64 t; cvta.to.shared.u64 t, %1; cvt.u32.u64 %0, t; }"
        : "=r"(a) : "l"(p));
    return a;
}
__device__ __forceinline__ void cp_async16(uint32_t dst, const void* src) {
    asm volatile("cp.async.cg.shared.global [%0], [%1], 16;"
                 :: "r"(dst), "l"(src));
}
__device__ __forceinline__ void ldsm_x4(uint32_t& r0, uint32_t& r1,
                                        uint32_t& r2, uint32_t& r3,
                                        uint32_t addr) {
    asm volatile("ldmatrix.sync.aligned.m8n8.x4.shared.b16 {%0,%1,%2,%3}, [%4];"
                 : "=r"(r0), "=r"(r1), "=r"(r2), "=r"(r3) : "r"(addr));
}
__device__ __forceinline__ void ldsm_x4_t(uint32_t& r0, uint32_t& r1,
                                          uint32_t& r2, uint32_t& r3,
                                          uint32_t addr) {
    asm volatile("ldmatrix.sync.aligned.m8n8.x4.trans.shared.b16 {%0,%1,%2,%3}, [%4];"
                 : "=r"(r0), "=r"(r1), "=r"(r2), "=r"(r3) : "r"(addr));
}
__device__ __forceinline__ void mma16816(float* d,
                                         uint32_t a0, uint32_t a1,
                                         uint32_t a2, uint32_t a3,
                                         uint32_t b0, uint32_t b1) {
    asm volatile(
        "mma.sync.aligned.m16n8k16.row.col.f32.bf16.bf16.f32 "
        "{%0,%1,%2,%3}, {%4,%5,%6,%7}, {%8,%9}, {%0,%1,%2,%3};"
        : "+f"(d[0]), "+f"(d[1]), "+f"(d[2]), "+f"(d[3])
        : "r"(a0), "r"(a1), "r"(a2), "r"(a3), "r"(b0), "r"(b1));
}

// ---------------------------------------------------------------------------
// prep kernels (merged launches)
// ---------------------------------------------------------------------------
__global__ void bn_prep_all_kernel(const float* __restrict__ qg, const float* __restrict__ qb,
                                   const float* __restrict__ qm, const float* __restrict__ qv,
                                   const float* __restrict__ kg, const float* __restrict__ kb,
                                   const float* __restrict__ km, const float* __restrict__ kv,
                                   const float* __restrict__ pg, const float* __restrict__ pb,
                                   const float* __restrict__ pm, const float* __restrict__ pv,
                                   const float* __restrict__ pbias,
                                   float* __restrict__ bnqk, float* __restrict__ bnp)
{
    int d = threadIdx.x;
    if (d >= C_) return;
    if (blockIdx.x == 0) {
        float s = qg[d] * rsqrtf(qv[d] + 1e-5f);
        bnqk[d]      = s;
        bnqk[C_ + d] = qb[d] - qm[d] * s;
    } else if (blockIdx.x == 1) {
        float s = kg[d] * rsqrtf(kv[d] + 1e-5f);
        bnqk[2 * C_ + d] = s;
        bnqk[3 * C_ + d] = kb[d] - km[d] * s;
    } else {
        float s = pg[d] * rsqrtf(pv[d] + 1e-5f);
        bnp[d]      = s;
        bnp[C_ + d] = fmaf(s, pbias[d], pb[d] - pm[d] * s);
    }
}

__global__ void split_w_all_kernel(const float* __restrict__ Wq,
                                   const float* __restrict__ Wk,
                                   const float* __restrict__ Wp,
                                   __nv_bfloat16* __restrict__ Aq,
                                   __nv_bfloat16* __restrict__ Ak,
                                   __nv_bfloat16* __restrict__ Ap)
{
    int i = blockIdx.x * 256 + threadIdx.x;
    if (i >= C_ * C_) return;
    const float* W = (blockIdx.y == 0) ? Wq : (blockIdx.y == 1) ? Wk : Wp;
    __nv_bfloat16* A = (blockIdx.y == 0) ? Aq : (blockIdx.y == 1) ? Ak : Ap;
    int d = i / C_, c = i % C_;
    float w = W[i];
    __nv_bfloat16 b1 = __float2bfloat16(w);
    float r = w - __bfloat162float(b1);
    __nv_bfloat16 b2 = __float2bfloat16(r);
    float r2 = r - __bfloat162float(b2);
    __nv_bfloat16 b3 = __float2bfloat16(r2);
    size_t base = (size_t)d * (3 * C_) + c;
    A[base]          = b1;
    A[base + C_]     = b2;
    A[base + 2 * C_] = b3;
}

__global__ void split_x_kernel(const float* __restrict__ x,
                               __nv_bfloat16* __restrict__ xs)
{
    size_t i = ((size_t)blockIdx.x * 256 + threadIdx.x) * 4;
    float4 v = *(const float4*)(x + i);
    float vv[4] = {v.x, v.y, v.z, v.w};
    __nv_bfloat16 o1[4], o2[4], o3[4];
#pragma unroll
    for (int e = 0; e < 4; ++e) {
        __nv_bfloat16 b1 = __float2bfloat16(vv[e]);
        float r = vv[e] - __bfloat162float(b1);
        __nv_bfloat16 b2 = __float2bfloat16(r);
        float r2 = r - __bfloat162float(b2);
        o1[e] = b1; o2[e] = b2; o3[e] = __float2bfloat16(r2);
    }
    *(uint2*)(xs + i)                    = *(uint2*)o1;
    *(uint2*)(xs + (size_t)TBCN + i)     = *(uint2*)o2;
    *(uint2*)(xs + 2 * (size_t)TBCN + i) = *(uint2*)o3;
}

// ---------------------------------------------------------------------------
// DUAL-output HMMA GEMM for q+k, occupancy-2 version.
// CTA tile 64(m) x 128(n), 256 threads, 8 warps (4m x 2n),
// warp tile 16(m) x 64(n) per output.  3-stage cp.async pipeline.
// Stage: [Aq 8KB][Ak 8KB][B 16KB] = 32KB; 3 stages = 96KB; 2 CTAs/SM.
// ---------------------------------------------------------------------------
#define DSTAGE 32768
#define DSMEM  98304

__constant__ int c_IM[6] = {0, 0, 1, 0, 1, 2};
__constant__ int c_JM[6] = {0, 1, 0, 2, 1, 0};

__device__ __forceinline__ void dual_load_chunk(const __nv_bfloat16* __restrict__ Aq,
                                                const __nv_bfloat16* __restrict__ Ak,
                                                const __nv_bfloat16* __restrict__ Bx,
                                                int d0, int n0g, int tb, int kc,
                                                uint32_t stage, int tid)
{
    const int t = kc / 6, ks = kc % 6;
    const int i = c_IM[t], j = c_JM[t];
    const char* AgQ = (const char*)(Aq + (size_t)d0 * 1152 + i * 384 + ks * 64);
    const char* AgK = (const char*)(Ak + (size_t)d0 * 1152 + i * 384 + ks * 64);
    const char* Bg  = (const char*)(Bx + (size_t)j * TBCN +
                                    ((size_t)tb * C_ + ks * 64) * N_ + n0g);
    // A tiles: 64 rows x 8 segs = 512 xfers; 2 per thread per output
#pragma unroll
    for (int q = 0; q < 2; ++q) {
        int idx = q * 256 + tid;
        int row = idx >> 3, seg = idx & 7;
        uint32_t off = (uint32_t)(row * 128) + (uint32_t)((seg ^ (row & 7)) << 4);
        cp_async16(stage + off,        AgQ + (size_t)row * 2304 + seg * 16);
        cp_async16(stage + 8192 + off, AgK + (size_t)row * 2304 + seg * 16);
    }
    // B tile: 64 k-rows x 16 segs = 1024 xfers; 4 per thread
#pragma unroll
    for (int q = 0; q < 4; ++q) {
        int idx = q * 256 + tid;
        int row = idx >> 4, seg = idx & 15;
        uint32_t off = (uint32_t)(row * 256) + (uint32_t)((seg ^ (row & 7)) << 4);
        cp_async16(stage + 16384 + off, Bg + (size_t)row * 512 + seg * 16);
    }
}

__global__ __launch_bounds__(256, 2)
void gemm_qk_dual_kernel(const __nv_bfloat16* __restrict__ Aq,
                         const __nv_bfloat16* __restrict__ Ak,
                         const __nv_bfloat16* __restrict__ Bx,
                         const float* __restrict__ bn,
                         float* __restrict__ outq,
                         float* __restrict__ outk)
{
    extern __shared__ char smem[];
    const uint32_t sbase = smem_to_u32(smem);
    const int tid  = threadIdx.x;
    const int wid  = tid >> 5;
    const int lane = tid & 31;
    const int nT = blockIdx.x, mT = blockIdx.y, tb = blockIdx.z;
    const int d0  = mT * 64;
    const int n0g = nT * 128;
    const int wm = wid & 3;      // 4 m-warps x 16 rows = 64
    const int wn = wid >> 2;     // 2 n-warps x 64 cols = 128
    const int nch = 36;

    float accq[8][4], acck[8][4];
#pragma unroll
    for (int p = 0; p < 8; ++p)
#pragma unroll
        for (int q = 0; q < 4; ++q) { accq[p][q] = 0.f; acck[p][q] = 0.f; }

    dual_load_chunk(Aq, Ak, Bx, d0, n0g, tb, 0, sbase, tid);
    asm volatile("cp.async.commit_group;");
    dual_load_chunk(Aq, Ak, Bx, d0, n0g, tb, 1, sbase + DSTAGE, tid);
    asm volatile("cp.async.commit_group;");

    for (int kc = 0; kc < nch; ++kc) {
        asm volatile("cp.async.wait_group 1;");
        __syncthreads();

        if (kc + 2 < nch)
            dual_load_chunk(Aq, Ak, Bx, d0, n0g, tb, kc + 2,
                            sbase + (uint32_t)((kc + 2) % 3) * DSTAGE, tid);
        asm volatile("cp.async.commit_group;");

        const uint32_t aqb = sbase + (uint32_t)(kc % 3) * DSTAGE;
        const uint32_t akb = aqb + 8192;
        const uint32_t bbf = aqb + 16384;

#pragma unroll
        for (int kk = 0; kk < 4; ++kk) {
            uint32_t aq[4], ak[4];
            {
                int row = wm * 16 + (lane & 15);
                int seg = kk * 2 + (lane >> 4);
                uint32_t aoff = (uint32_t)(row * 128) + (uint32_t)((seg ^ (row & 7)) << 4);
                ldsm_x4(aq[0], aq[1], aq[2], aq[3], aqb + aoff);
                ldsm_x4(ak[0], ak[1], ak[2], ak[3], akb + aoff);
            }
            uint32_t b[4][4];
#pragma unroll
            for (int p = 0; p < 4; ++p) {
                int krow = kk * 16 + ((lane >> 3) & 1) * 8 + (lane & 7);
                int seg  = wn * 8 + p * 2 + (lane >> 4);
                uint32_t addr = bbf + (uint32_t)(krow * 256) +
                                (uint32_t)((seg ^ (krow & 7)) << 4);
                ldsm_x4_t(b[p][0], b[p][1], b[p][2], b[p][3], addr);
            }
#pragma unroll
            for (int p = 0; p < 4; ++p) {
                mma16816(accq[p * 2],     aq[0], aq[1], aq[2], aq[3], b[p][0], b[p][1]);
                mma16816(accq[p * 2 + 1], aq[0], aq[1], aq[2], aq[3], b[p][2], b[p][3]);
                mma16816(acck[p * 2],     ak[0], ak[1], ak[2], ak[3], b[p][0], b[p][1]);
                mma16816(acck[p * 2 + 1], ak[0], ak[1], ak[2], ak[3], b[p][2], b[p][3]);
            }
        }
    }

    // Epilogue: BN, store both outputs
#pragma unroll
    for (int rr = 0; rr < 2; ++rr) {
        const int d = d0 + wm * 16 + (lane >> 2) + rr * 8;
        const float scq = bn[d],          shq = bn[C_ + d];
        const float sck = bn[2 * C_ + d], shk = bn[3 * C_ + d];
        float* opq = outq + ((size_t)tb * C_ + d) * N_ + n0g + wn * 64 + (lane & 3) * 2;
        float* opk = outk + ((size_t)tb * C_ + d) * N_ + n0g + wn * 64 + (lane & 3) * 2;
#pragma unroll
        for (int j = 0; j < 8; ++j) {
            float2 oq, ok;
            oq.x = fmaf(accq[j][rr * 2 + 0], scq, shq);
            oq.y = fmaf(accq[j][rr * 2 + 1], scq, shq);
            ok.x = fmaf(acck[j][rr * 2 + 0], sck, shk);
            ok.y = fmaf(acck[j][rr * 2 + 1], sck, shk);
            *(float2*)(opq + j * 8) = oq;
            *(float2*)(opk + j * 8) = ok;
        }
    }
}

// ---------------------------------------------------------------------------
// Single-output HMMA GEMM (proj), occupancy-3 version.
// CTA tile 64(m) x 128(n), 256 threads, 8 warps (4m x 2n), warp 16x64.
// Stage: [A 8KB][B 16KB] = 24KB; 3 stages = 72KB; 3 CTAs/SM.
// ---------------------------------------------------------------------------
#define PSTAGE 24576
#define PSMEM  73728

__device__ __forceinline__ void proj_load_chunk(const __nv_bfloat16* __restrict__ A,
                                                const __nv_bfloat16* __restrict__ Bx,
                                                int d0, int n0g, int tb, int kc,
                                                uint32_t stage, int tid)
{
    const int t = kc / 6, ks = kc % 6;
    const char* Ag = (const char*)(A + (size_t)d0 * 1152 + t * 384 + ks * 64);
    const char* Bg = (const char*)(Bx + ((size_t)tb * C_ + ks * 64) * N_ + n0g);
#pragma unroll
    for (int q = 0; q < 2; ++q) {
        int idx = q * 256 + tid;
        int row = idx >> 3, seg = idx & 7;
        uint32_t off = (uint32_t)(row * 128) + (uint32_t)((seg ^ (row & 7)) << 4);
        cp_async16(stage + off, Ag + (size_t)row * 2304 + seg * 16);
    }
#pragma unroll
    for (int q = 0; q < 4; ++q) {
        int idx = q * 256 + tid;
        int row = idx >> 4, seg = idx & 15;
        uint32_t off = (uint32_t)(row * 256) + (uint32_t)((seg ^ (row & 7)) << 4);
        cp_async16(stage + 8192 + off, Bg + (size_t)row * 512 + seg * 16);
    }
}

__global__ __launch_bounds__(256, 3)
void gemm_proj_kernel(const __nv_bfloat16* __restrict__ A,
                      const __nv_bfloat16* __restrict__ Bx,
                      const float* __restrict__ bn,
                      float* __restrict__ out)
{
    extern __shared__ char smem[];
    const uint32_t sbase = smem_to_u32(smem);
    const int tid  = threadIdx.x;
    const int wid  = tid >> 5;
    const int lane = tid & 31;
    const int nT = blockIdx.x, mT = blockIdx.y, tb = blockIdx.z;
    const int d0  = mT * 64;
    const int n0g = nT * 128;
    const int wm = wid & 3;
    const int wn = wid >> 2;
    const int nch = 18;

    float acc[8][4];
#pragma unroll
    for (int p = 0; p < 8; ++p)
#pragma unroll
        for (int q = 0; q < 4; ++q) acc[p][q] = 0.f;

    proj_load_chunk(A, Bx, d0, n0g, tb, 0, sbase, tid);
    asm volatile("cp.async.commit_group;");
    proj_load_chunk(A, Bx, d0, n0g, tb, 1, sbase + PSTAGE, tid);
    asm volatile("cp.async.commit_group;");

    for (int kc = 0; kc < nch; ++kc) {
        asm volatile("cp.async.wait_group 1;");
        __syncthreads();

        if (kc + 2 < nch)
            proj_load_chunk(A, Bx, d0, n0g, tb, kc + 2,
                            sbase + (uint32_t)((kc + 2) % 3) * PSTAGE, tid);
        asm volatile("cp.async.commit_group;");

        const uint32_t ab = sbase + (uint32_t)(kc % 3) * PSTAGE;
        const uint32_t bbf = ab + 8192;

#pragma unroll
        for (int kk = 0; kk < 4; ++kk) {
            uint32_t a[4];
            {
                int row = wm * 16 + (lane & 15);
                int seg = kk * 2 + (lane >> 4);
                uint32_t aoff = (uint32_t)(row * 128) + (uint32_t)((seg ^ (row & 7)) << 4);
                ldsm_x4(a[0], a[1], a[2], a[3], ab + aoff);
            }
            uint32_t b[4][4];
#pragma unroll
            for (int p = 0; p < 4; ++p) {
                int krow = kk * 16 + ((lane >> 3) & 1) * 8 + (lane & 7);
                int seg  = wn * 8 + p * 2 + (lane >> 4);
                uint32_t addr = bbf + (uint32_t)(krow * 256) +
                                (uint32_t)((seg ^ (krow & 7)) << 4);
                ldsm_x4_t(b[p][0], b[p][1], b[p][2], b[p][3], addr);
            }
#pragma unroll
            for (int p = 0; p < 4; ++p) {
                mma16816(acc[p * 2],     a[0], a[1], a[2], a[3], b[p][0], b[p][1]);
                mma16816(acc[p * 2 + 1], a[0], a[1], a[2], a[3], b[p][2], b[p][3]);
            }
        }
    }

#pragma unroll
    for (int rr = 0; rr < 2; ++rr) {
        const int d = d0 + wm * 16 + (lane >> 2) + rr * 8;
        const float sc = bn[d];
        const float sh = bn[C_ + d];
        float* op = out + ((size_t)tb * C_ + d) * N_ + n0g + wn * 64 + (lane & 3) * 2;
#pragma unroll
        for (int j = 0; j < 8; ++j) {
            float2 o;
            o.x = fmaf(acc[j][rr * 2 + 0], sc, sh);
            o.y = fmaf(acc[j][rr * 2 + 1], sc, sh);
            *(float2*)(op + j * 8) = o;
        }
    }
}

// ---------------------------------------------------------------------------
// Fused: q-LIF -> head-sum -> attn-LIF -> k-LIF -> y (bf16)
// ---------------------------------------------------------------------------
__global__ void attn_fuse_kernel(const float* __restrict__ qlin,
                                 const float* __restrict__ klin,
                                 __nv_bfloat16* __restrict__ y)
{
    const int bh = blockIdx.x;
    const int b  = bh >> 3;
    const int hd = bh & 7;
    const int n  = threadIdx.x;
    const size_t tstr = (size_t)BCN;

    float qs[4] = {0.f, 0.f, 0.f, 0.f};
    const size_t base = ((size_t)b * C_ + hd * CH) * N_ + n;

    for (int c = 0; c < CH; ++c) {
        const size_t idx = base + (size_t)c * N_;
        float v = 0.f;
#pragma unroll
        for (int t = 0; t < T_; ++t) {
            const float xq = qlin[idx + (size_t)t * tstr];
            const float h  = v + (xq - v) * 0.5f;
            const bool  sp = (h >= 1.0f);
            qs[t] += sp ? 1.f : 0.f;
            v = sp ? 0.f : h;
        }
    }

    float a[4];
    {
        float v = 0.f;
#pragma unroll
        for (int t = 0; t < T_; ++t) {
            const float h = v + (qs[t] - v) * 0.5f;
            const bool sp = (h >= 0.5f);
            a[t] = sp ? 1.f : 0.f;
            v = sp ? 0.f : h;
        }
    }

    for (int c = 0; c < CH; ++c) {
        const size_t idx = base + (size_t)c * N_;
        float v = 0.f;
#pragma unroll
        for (int t = 0; t < T_; ++t) {
            const float xk = klin[idx + (size_t)t * tstr];
            const float h  = v + (xk - v) * 0.5f;
            const bool  sp = (h >= 1.0f);
            const float yv = (sp ? 1.f : 0.f) * a[t];
            y[idx + (size_t)t * tstr] = __float2bfloat16(yv);
            v = sp ? 0.f : h;
        }
    }
}

// ---------------------------------------------------------------------------
// Final LIF -> spikes to d_out
// ---------------------------------------------------------------------------
__global__ void final_lif_kernel(const float* __restrict__ p,
                                 float* __restrict__ o)
{
    const size_t i = (size_t)blockIdx.x * blockDim.x + threadIdx.x;
    float v = 0.f;
#pragma unroll
    for (int t = 0; t < T_; ++t) {
        const float x = p[i + (size_t)t * BCN];
        const float h = v + (x - v) * 0.5f;
        const bool sp = (h >= 1.0f);
        o[i + (size_t)t * BCN] = sp ? 1.f : 0.f;
        v = sp ? 0.f : h;
    }
}

// ---------------------------------------------------------------------------
extern "C" void kernel_launch(void* const* d_in, const int* in_sizes, int n_in,
                              void* d_out, int out_size)
{
    const float* x        = (const float*)d_in[0];
    const float* q_w      = (const float*)d_in[1];
    const float* q_gamma  = (const float*)d_in[2];
    const float* q_beta   = (const float*)d_in[3];
    const float* q_mean   = (const float*)d_in[4];
    const float* q_var    = (const float*)d_in[5];
    const float* k_w      = (const float*)d_in[6];
    const float* k_gamma  = (const float*)d_in[7];
    const float* k_beta   = (const float*)d_in[8];
    const float* k_mean   = (const float*)d_in[9];
    const float* k_var    = (const float*)d_in[10];
    const float* p_w      = (const float*)d_in[11];
    const float* p_gamma  = (const float*)d_in[12];
    const float* p_beta   = (const float*)d_in[13];
    const float* p_mean   = (const float*)d_in[14];
    const float* p_var    = (const float*)d_in[15];
    const float* p_b      = (const float*)d_in[16];

    float *qlin, *klin, *bnqk, *bnp;
    __nv_bfloat16 *xs, *y, *Aq, *Ak, *Ap;
    cudaGetSymbolAddress((void**)&qlin, g_qlin);
    cudaGetSymbolAddress((void**)&klin, g_klin);
    cudaGetSymbolAddress((void**)&xs, g_xs);
    cudaGetSymbolAddress((void**)&y, g_y);
    cudaGetSymbolAddress((void**)&Aq, g_Aq);
    cudaGetSymbolAddress((void**)&Ak, g_Ak);
    cudaGetSymbolAddress((void**)&Ap, g_Ap);
    cudaGetSymbolAddress((void**)&bnqk, g_bnqk);
    cudaGetSymbolAddress((void**)&bnp, g_bnp);

    cudaFuncSetAttribute(gemm_qk_dual_kernel,
                         cudaFuncAttributeMaxDynamicSharedMemorySize, DSMEM);
    cudaFuncSetAttribute(gemm_proj_kernel,
                         cudaFuncAttributeMaxDynamicSharedMemorySize, PSMEM);

    // prep (merged: 3 launches)
    bn_prep_all_kernel<<<3, C_>>>(q_gamma, q_beta, q_mean, q_var,
                                  k_gamma, k_beta, k_mean, k_var,
                                  p_gamma, p_beta, p_mean, p_var, p_b,
                                  bnqk, bnp);
    split_w_all_kernel<<<dim3((C_ * C_ + 255) / 256, 3), 256>>>(q_w, k_w, p_w,
                                                                Aq, Ak, Ap);
    split_x_kernel<<<TBCN / 1024, 256>>>(x, xs);

    // dual q+k GEMM (shared B), 64-row m-tiles, occ 2
    gemm_qk_dual_kernel<<<dim3(2, 6, 128), 256, DSMEM>>>(Aq, Ak, xs, bnqk,
                                                         qlin, klin);

    attn_fuse_kernel<<<B_ * HEADS, N_>>>(qlin, klin, y);

    // proj GEMM (3-term), 64-row m-tiles, occ 3
    gemm_proj_kernel<<<dim3(2, 6, 128), 256, PSMEM>>>(Ap, y, bnp, qlin);

    final_lif_kernel<<<BCN / 256, 256>>>(qlin, (float*)d_out);
}